// round 1
// baseline (speedup 1.0000x reference)
#include <cuda_runtime.h>
#include <cstdint>
#include <cstdio>

#define N_NODES  200000
#define N_EDGES  800000
#define N_GRAPHS 4096
#define MAXDEG   5

// ---------------- scratch (static __device__, no allocs) ----------------
__device__ float g_msg[N_NODES * 256];
__device__ float g_h0[N_NODES * 128];
__device__ float g_h1[N_NODES * 128];
__device__ float g_h2[N_NODES * 256];
__device__ float g_h3[N_NODES * 256];
__device__ float g_pool[N_GRAPHS * 256];
__device__ int   g_deg[N_NODES];
__device__ int   g_perm[N_NODES];
// [0..5] = bucket counts, [8..13] = bucket offsets, [16..21] = fill cursors
__device__ int   g_meta[64];

// ---------------- helpers ----------------
__device__ __forceinline__ void red_add_v4(float* addr, float4 v) {
    asm volatile("red.global.add.v4.f32 [%0], {%1,%2,%3,%4};"
                 :: "l"(addr), "f"(v.x), "f"(v.y), "f"(v.z), "f"(v.w)
                 : "memory");
}

// ---------------- degree + bucketing ----------------
__global__ void k_zero_deg_meta() {
    int i = blockIdx.x * 256 + threadIdx.x;
    if (i < N_NODES) g_deg[i] = 0;
    if (i < 64) g_meta[i] = 0;
}

__global__ void k_deg(const int* __restrict__ dst) {
    int e = blockIdx.x * 256 + threadIdx.x;
    if (e < N_EDGES) atomicAdd(&g_deg[dst[e]], 1);
}

__global__ void k_bcount() {
    int i = blockIdx.x * 256 + threadIdx.x;
    if (i < N_NODES) {
        int d = min(g_deg[i], MAXDEG);
        atomicAdd(&g_meta[d], 1);
    }
}

__global__ void k_offsets() {
    int s = 0;
    for (int d = 0; d <= MAXDEG; d++) { g_meta[8 + d] = s; s += g_meta[d]; }
}

__global__ void k_fill() {
    int i = blockIdx.x * 256 + threadIdx.x;
    if (i < N_NODES) {
        int d = min(g_deg[i], MAXDEG);
        int p = atomicAdd(&g_meta[16 + d], 1);
        g_perm[g_meta[8 + d] + p] = i;
    }
}

// ---------------- zero kernels ----------------
__global__ void k_zero_msg(int n_f4) {  // n_f4 = N_NODES*CIN/4
    int i = blockIdx.x * 256 + threadIdx.x;
    if (i < n_f4) reinterpret_cast<float4*>(g_msg)[i] = make_float4(0.f, 0.f, 0.f, 0.f);
}

__global__ void k_zero_pool() {
    int i = blockIdx.x * 256 + threadIdx.x;
    if (i < N_GRAPHS * 256 / 4)
        reinterpret_cast<float4*>(g_pool)[i] = make_float4(0.f, 0.f, 0.f, 0.f);
}

// ---------------- edge scatter (segment sum) ----------------
template <int CIN>
__global__ void k_scatter(const float* __restrict__ h,
                          const int* __restrict__ src,
                          const int* __restrict__ dst) {
    int t = blockIdx.x * 256 + threadIdx.x;          // E * CIN/4 threads
    const int PER = CIN / 4;
    int e = t / PER;
    int f = (t % PER) * 4;
    if (e >= N_EDGES) return;
    int s = src[e], d = dst[e];
    float4 v = *reinterpret_cast<const float4*>(h + (size_t)s * CIN + f);
    red_add_v4(g_msg + (size_t)d * CIN + f, v);
}

// ---------------- bucketed SGEMM: out[node] = [msg|hprev] @ [Wl[d];Wr[d]] + bl[d] ----------------
template <int CIN, int COUT>
__global__ __launch_bounds__(256)
void mf_gemm(const float* __restrict__ hprev,
             const float* __restrict__ Wl, const float* __restrict__ bl,
             const float* __restrict__ Wr, float* __restrict__ out) {
    const int d  = blockIdx.y;
    const int M  = g_meta[d];
    const int m0 = blockIdx.x * 64;
    if (m0 >= M) return;
    const int base = g_meta[8 + d];
    const int n0   = blockIdx.z * 64;
    const int tid  = threadIdx.x;
    const int tx   = tid & 15, ty = tid >> 4;

    __shared__ float As[16][64];
    __shared__ float Bs[16][64];
    __shared__ int   rows_s[64];

    if (tid < 64) {
        int mi = m0 + tid;
        rows_s[tid] = (mi < M) ? g_perm[base + mi] : -1;
    }
    __syncthreads();

    const int arow = tid >> 2;          // 0..63
    const int akk  = (tid & 3) << 2;    // 0,4,8,12
    const int bkk  = tid >> 4;          // 0..15
    const int bn   = (tid & 15) << 2;   // 0..60
    const int anode = rows_s[arow];

    float acc[4][4];
#pragma unroll
    for (int i = 0; i < 4; i++)
#pragma unroll
        for (int j = 0; j < 4; j++) acc[i][j] = 0.f;

    for (int k0 = 0; k0 < 2 * CIN; k0 += 16) {
        const bool left = (k0 < CIN);
        const int  kl   = left ? k0 : k0 - CIN;
        // A tile (gathered rows, transposed store into As[k][m])
        float4 av = make_float4(0.f, 0.f, 0.f, 0.f);
        if (anode >= 0) {
            const float* ap = (left ? g_msg : hprev) + (size_t)anode * CIN + kl + akk;
            av = *reinterpret_cast<const float4*>(ap);
        }
        As[akk + 0][arow] = av.x;
        As[akk + 1][arow] = av.y;
        As[akk + 2][arow] = av.z;
        As[akk + 3][arow] = av.w;
        // B tile
        const float* wp = (left ? Wl : Wr) + ((size_t)d * CIN + kl + bkk) * COUT + n0 + bn;
        *reinterpret_cast<float4*>(&Bs[bkk][bn]) = *reinterpret_cast<const float4*>(wp);
        __syncthreads();

#pragma unroll
        for (int kk = 0; kk < 16; kk++) {
            float4 a = *reinterpret_cast<const float4*>(&As[kk][ty * 4]);
            float4 b = *reinterpret_cast<const float4*>(&Bs[kk][tx * 4]);
            acc[0][0] += a.x * b.x; acc[0][1] += a.x * b.y; acc[0][2] += a.x * b.z; acc[0][3] += a.x * b.w;
            acc[1][0] += a.y * b.x; acc[1][1] += a.y * b.y; acc[1][2] += a.y * b.z; acc[1][3] += a.y * b.w;
            acc[2][0] += a.z * b.x; acc[2][1] += a.z * b.y; acc[2][2] += a.z * b.z; acc[2][3] += a.z * b.w;
            acc[3][0] += a.w * b.x; acc[3][1] += a.w * b.y; acc[3][2] += a.w * b.z; acc[3][3] += a.w * b.w;
        }
        __syncthreads();
    }

    float4 bv = *reinterpret_cast<const float4*>(bl + d * COUT + n0 + tx * 4);
#pragma unroll
    for (int i = 0; i < 4; i++) {
        int mi = m0 + ty * 4 + i;
        if (mi < M) {
            int node = rows_s[ty * 4 + i];
            float4 o = make_float4(acc[i][0] + bv.x, acc[i][1] + bv.y,
                                   acc[i][2] + bv.z, acc[i][3] + bv.w);
            *reinterpret_cast<float4*>(out + (size_t)node * COUT + n0 + tx * 4) = o;
        }
    }
}

// ---------------- global add pool over batch ----------------
__global__ void k_pool(const int* __restrict__ batch) {
    int t = blockIdx.x * 256 + threadIdx.x;   // N_NODES * 64 threads
    int i = t >> 6;
    int f = (t & 63) * 4;
    if (i >= N_NODES) return;
    float4 v = *reinterpret_cast<const float4*>(g_h3 + (size_t)i * 256 + f);
    red_add_v4(g_pool + (size_t)batch[i] * 256 + f, v);
}

// ---------------- final: concat @ Wf + bf, softmax ----------------
__global__ void k_final(const int* __restrict__ batch,
                        const float* __restrict__ Wf, const float* __restrict__ bf,
                        float* __restrict__ out) {
    int gt   = blockIdx.x * 256 + threadIdx.x;
    int node = gt >> 5;
    int lane = gt & 31;
    if (node >= N_NODES) return;

    float a0 = 0.f, a1 = 0.f;
    const int g = batch[node];

#pragma unroll 4
    for (int k = lane; k < 128; k += 32) {
        float v = g_h0[(size_t)node * 128 + k];
        float2 w = *reinterpret_cast<const float2*>(Wf + 2 * (0 + k));
        a0 += v * w.x; a1 += v * w.y;
    }
#pragma unroll 4
    for (int k = lane; k < 128; k += 32) {
        float v = g_h1[(size_t)node * 128 + k];
        float2 w = *reinterpret_cast<const float2*>(Wf + 2 * (128 + k));
        a0 += v * w.x; a1 += v * w.y;
    }
#pragma unroll 8
    for (int k = lane; k < 256; k += 32) {
        float v = g_h2[(size_t)node * 256 + k];
        float2 w = *reinterpret_cast<const float2*>(Wf + 2 * (256 + k));
        a0 += v * w.x; a1 += v * w.y;
    }
#pragma unroll 8
    for (int k = lane; k < 256; k += 32) {
        float v = g_h3[(size_t)node * 256 + k];
        float2 w = *reinterpret_cast<const float2*>(Wf + 2 * (512 + k));
        a0 += v * w.x; a1 += v * w.y;
    }
#pragma unroll 8
    for (int k = lane; k < 256; k += 32) {
        float v = g_pool[(size_t)g * 256 + k];
        float2 w = *reinterpret_cast<const float2*>(Wf + 2 * (768 + k));
        a0 += v * w.x; a1 += v * w.y;
    }

#pragma unroll
    for (int o = 16; o > 0; o >>= 1) {
        a0 += __shfl_xor_sync(0xFFFFFFFFu, a0, o);
        a1 += __shfl_xor_sync(0xFFFFFFFFu, a1, o);
    }
    if (lane == 0) {
        a0 += bf[0]; a1 += bf[1];
        float m  = fmaxf(a0, a1);
        float e0 = expf(a0 - m), e1 = expf(a1 - m);
        float s  = e0 + e1;
        out[(size_t)node * 2 + 0] = e0 / s;
        out[(size_t)node * 2 + 1] = e1 / s;
    }
}

// ---------------- launch ----------------
extern "C" void kernel_launch(void* const* d_in, const int* in_sizes, int n_in,
                              void* d_out, int out_size) {
    (void)in_sizes; (void)n_in; (void)out_size;
    const float* x    = (const float*)d_in[0];
    const int*   ei   = (const int*)d_in[1];
    const int*   batch= (const int*)d_in[2];
    const float* Wl0 = (const float*)d_in[3];
    const float* bl0 = (const float*)d_in[4];
    const float* Wr0 = (const float*)d_in[5];
    const float* Wl1 = (const float*)d_in[6];
    const float* bl1 = (const float*)d_in[7];
    const float* Wr1 = (const float*)d_in[8];
    const float* Wl2 = (const float*)d_in[9];
    const float* bl2 = (const float*)d_in[10];
    const float* Wr2 = (const float*)d_in[11];
    const float* Wl3 = (const float*)d_in[12];
    const float* bl3 = (const float*)d_in[13];
    const float* Wr3 = (const float*)d_in[14];
    const float* Wf  = (const float*)d_in[15];
    const float* bf  = (const float*)d_in[16];
    float* out = (float*)d_out;

    const int* src = ei;
    const int* dst = ei + N_EDGES;

    float *h0, *h1, *h2, *h3;
    cudaGetSymbolAddress((void**)&h0, g_h0);
    cudaGetSymbolAddress((void**)&h1, g_h1);
    cudaGetSymbolAddress((void**)&h2, g_h2);
    cudaGetSymbolAddress((void**)&h3, g_h3);

    const int NB_N = (N_NODES + 255) / 256;
    const int NB_E = (N_EDGES + 255) / 256;
    const int TILES_M = (N_NODES + 63) / 64;   // 3125

    // degree + buckets
    k_zero_deg_meta<<<NB_N, 256>>>();
    k_deg<<<NB_E, 256>>>(dst);
    k_bcount<<<NB_N, 256>>>();
    k_offsets<<<1, 1>>>();
    k_fill<<<NB_N, 256>>>();

    // layer 0: CIN=64 -> COUT=128
    k_zero_msg<<<(N_NODES * 16 + 255) / 256, 256>>>(N_NODES * 16);
    k_scatter<64><<<(N_EDGES * 16 + 255) / 256, 256>>>(x, src, dst);
    mf_gemm<64, 128><<<dim3(TILES_M, 6, 2), 256>>>(x, Wl0, bl0, Wr0, h0);

    // layer 1: 128 -> 128
    k_zero_msg<<<(N_NODES * 32 + 255) / 256, 256>>>(N_NODES * 32);
    k_scatter<128><<<(N_EDGES * 32 + 255) / 256, 256>>>(h0, src, dst);
    mf_gemm<128, 128><<<dim3(TILES_M, 6, 2), 256>>>(h0, Wl1, bl1, Wr1, h1);

    // layer 2: 128 -> 256
    k_zero_msg<<<(N_NODES * 32 + 255) / 256, 256>>>(N_NODES * 32);
    k_scatter<128><<<(N_EDGES * 32 + 255) / 256, 256>>>(h1, src, dst);
    mf_gemm<128, 256><<<dim3(TILES_M, 6, 4), 256>>>(h1, Wl2, bl2, Wr2, h2);

    // layer 3: 256 -> 256
    k_zero_msg<<<(N_NODES * 64 + 255) / 256, 256>>>(N_NODES * 64);
    k_scatter<256><<<(N_EDGES * 64 + 255) / 256, 256>>>(h2, src, dst);
    mf_gemm<256, 256><<<dim3(TILES_M, 6, 4), 256>>>(h2, Wl3, bl3, Wr3, h3);

    // pool + final
    k_zero_pool<<<(N_GRAPHS * 64 + 255) / 256, 256>>>();
    k_pool<<<(N_NODES * 64 + 255) / 256, 256>>>(batch);
    k_final<<<(N_NODES * 32 + 255) / 256, 256>>>(batch, Wf, bf, out);
}

// round 4
// speedup vs baseline: 1.2317x; 1.2317x over previous
#include <cuda_runtime.h>
#include <cuda_bf16.h>
#include <cstdint>

#define N_NODES  200000
#define N_EDGES  800000
#define N_GRAPHS 4096
#define MAXDEG   5

// ---------------- scratch (static __device__, no allocs) ----------------
__device__ float g_msg[N_NODES * 256];
__device__ float g_h0[N_NODES * 128];
__device__ float g_h1[N_NODES * 128];
__device__ float g_h2[N_NODES * 256];
__device__ float g_h3[N_NODES * 256];
__device__ float g_pool[N_GRAPHS * 256];
__device__ int   g_deg[N_NODES];
__device__ int   g_perm[N_NODES];
// [0..5] = bucket counts, [8..13] = bucket offsets, [16..21] = fill cursors
__device__ int   g_meta[64];

// split-bf16 transposed weights: per layer, [d][n][k] K-major (k spans 2*CIN: Wl then Wr)
#define WOFF0 0
#define WOFF1 98304
#define WOFF2 294912
#define WOFF3 688128
#define WTOT  1474560
__device__ __nv_bfloat16 g_whi[WTOT];
__device__ __nv_bfloat16 g_wlo[WTOT];

// ---------------- helpers (portable PTX only — no sm_103a-specific ops) ----------------
__device__ __forceinline__ uint32_t smem_u32(const void* p) {
    uint32_t a;
    asm("{ .reg .u64 t; cvta.to.shared.u64 t, %1; cvt.u32.u64 %0, t; }" : "=r"(a) : "l"(p));
    return a;
}
__device__ __forceinline__ void red_add_v4(float* addr, float4 v) {
    asm volatile("red.global.add.v4.f32 [%0], {%1,%2,%3,%4};"
                 :: "l"(addr), "f"(v.x), "f"(v.y), "f"(v.z), "f"(v.w) : "memory");
}
__device__ __forceinline__ void ldsm_x4(uint32_t* r, uint32_t addr) {
    asm volatile("ldmatrix.sync.aligned.m8n8.x4.shared.b16 {%0,%1,%2,%3}, [%4];"
                 : "=r"(r[0]), "=r"(r[1]), "=r"(r[2]), "=r"(r[3]) : "r"(addr));
}
__device__ __forceinline__ void ldsm_x2(uint32_t* r, uint32_t addr) {
    asm volatile("ldmatrix.sync.aligned.m8n8.x2.shared.b16 {%0,%1}, [%2];"
                 : "=r"(r[0]), "=r"(r[1]) : "r"(addr));
}
__device__ __forceinline__ void mma_16816(float* c, const uint32_t* a, const uint32_t* b) {
    asm volatile("mma.sync.aligned.m16n8k16.row.col.f32.bf16.bf16.f32 "
                 "{%0,%1,%2,%3}, {%4,%5,%6,%7}, {%8,%9}, {%0,%1,%2,%3};"
                 : "+f"(c[0]), "+f"(c[1]), "+f"(c[2]), "+f"(c[3])
                 : "r"(a[0]), "r"(a[1]), "r"(a[2]), "r"(a[3]), "r"(b[0]), "r"(b[1]));
}

// ---------------- degree + bucketing ----------------
__global__ void k_zero_deg_meta() {
    int i = blockIdx.x * 256 + threadIdx.x;
    if (i < N_NODES) g_deg[i] = 0;
    if (i < 64) g_meta[i] = 0;
}
__global__ void k_deg(const int* __restrict__ dst) {
    int e = blockIdx.x * 256 + threadIdx.x;
    if (e < N_EDGES) atomicAdd(&g_deg[dst[e]], 1);
}
__global__ void k_bcount() {
    int i = blockIdx.x * 256 + threadIdx.x;
    if (i < N_NODES) atomicAdd(&g_meta[min(g_deg[i], MAXDEG)], 1);
}
__global__ void k_offsets() {
    int s = 0;
    for (int d = 0; d <= MAXDEG; d++) { g_meta[8 + d] = s; s += g_meta[d]; }
}
__global__ void k_fill() {
    int i = blockIdx.x * 256 + threadIdx.x;
    if (i < N_NODES) {
        int d = min(g_deg[i], MAXDEG);
        int p = atomicAdd(&g_meta[16 + d], 1);
        g_perm[g_meta[8 + d] + p] = i;
    }
}

// ---------------- zero kernels ----------------
__global__ void k_zero_msg(int n_f4) {
    int i = blockIdx.x * 256 + threadIdx.x;
    if (i < n_f4) reinterpret_cast<float4*>(g_msg)[i] = make_float4(0.f, 0.f, 0.f, 0.f);
}
__global__ void k_zero_pool() {
    int i = blockIdx.x * 256 + threadIdx.x;
    if (i < N_GRAPHS * 256 / 4)
        reinterpret_cast<float4*>(g_pool)[i] = make_float4(0.f, 0.f, 0.f, 0.f);
}

// ---------------- edge scatter (segment sum) ----------------
template <int CIN>
__global__ void k_scatter(const float* __restrict__ h,
                          const int* __restrict__ src,
                          const int* __restrict__ dst) {
    int t = blockIdx.x * 256 + threadIdx.x;
    const int PER = CIN / 4;
    int e = t / PER;
    int f = (t % PER) * 4;
    if (e >= N_EDGES) return;
    int s = src[e], d = dst[e];
    float4 v = *reinterpret_cast<const float4*>(h + (size_t)s * CIN + f);
    red_add_v4(g_msg + (size_t)d * CIN + f, v);
}

// ---------------- weight prep: transpose + bf16 hi/lo split ----------------
template <int CIN, int COUT>
__global__ void k_prep_w(const float* __restrict__ Wl, const float* __restrict__ Wr,
                         __nv_bfloat16* __restrict__ Whi, __nv_bfloat16* __restrict__ Wlo) {
    const int K = 2 * CIN;
    int t = blockIdx.x * 256 + threadIdx.x;
    if (t >= 6 * K * COUT) return;
    int n = t % COUT;
    int k = (t / COUT) % K;
    int d = t / (COUT * K);
    float v = (k < CIN) ? Wl[((size_t)d * CIN + k) * COUT + n]
                        : Wr[((size_t)d * CIN + (k - CIN)) * COUT + n];
    __nv_bfloat16 hi = __float2bfloat16_rn(v);
    float lo = v - __bfloat162float(hi);
    size_t o = ((size_t)(d * COUT + n)) * K + k;
    Whi[o] = hi;
    Wlo[o] = __float2bfloat16_rn(lo);
}

// ---------------- mma.sync bucketed GEMM (split-bf16, 3-term) ----------------
// out[node] = [msg(node) | hprev(node)] @ Wt[d]^T + bl[d]
// Block: 256 thr, tile 128(M) x 64(N), K chunk 64, warps 4(M) x 2(N), warp tile 32x32.
template <int CIN, int COUT>
__global__ __launch_bounds__(256)
void mf_gemm_mma(const float* __restrict__ hprev,
                 const __nv_bfloat16* __restrict__ Whi,
                 const __nv_bfloat16* __restrict__ Wlo,
                 const float* __restrict__ bl,
                 float* __restrict__ out) {
    constexpr int K     = 2 * CIN;
    constexpr int NCH   = K / 64;
    constexpr int NSLAB = COUT / 64;

    extern __shared__ char smem[];
    __shared__ int rows_s[128];
    char* smA_hi = smem;                 // [128][64] bf16, swizzled
    char* smA_lo = smem + 16384;
    char* smB_hi = smem + 32768;         // [64][64] bf16, swizzled
    char* smB_lo = smem + 40960;

    const int slab = blockIdx.x % NSLAB;        // slab fastest -> A-sharing blocks co-scheduled
    const int tile = blockIdx.x / NSLAB;
    const int d    = blockIdx.y;
    const int M    = g_meta[d];
    const int m0   = tile * 128;
    if (m0 >= M) return;
    const int base = g_meta[8 + d];
    const int n0g  = slab * 64;
    const int tid  = threadIdx.x;
    const int lane = tid & 31, wid = tid >> 5;
    const int wm   = wid & 3, wn = wid >> 2;

    if (tid < 128) {
        int mi = m0 + tid;
        rows_s[tid] = (mi < M) ? g_perm[base + mi] : -1;
    }

    const uint32_t sA_hi = smem_u32(smA_hi), sA_lo = smem_u32(smA_lo);
    const uint32_t sB_hi = smem_u32(smB_hi), sB_lo = smem_u32(smB_lo);

    float acc[2][4][4];
#pragma unroll
    for (int t = 0; t < 2; t++)
#pragma unroll
        for (int u = 0; u < 4; u++)
#pragma unroll
            for (int i = 0; i < 4; i++) acc[t][u][i] = 0.f;

    for (int c = 0; c < NCH; c++) {
        __syncthreads();   // rows_s ready (c=0) / previous chunk compute done

        // ---- A tile: gather 128 rows x 64 k fp32, split to bf16 hi/lo, swizzled store ----
        const bool  left = (c * 64 < CIN);
        const float* srcp = left ? g_msg : hprev;
        const int   kl   = c * 64 - (left ? 0 : CIN);
#pragma unroll
        for (int it = 0; it < 8; it++) {
            int idx = it * 256 + tid;
            int row = idx >> 4, f4 = idx & 15;
            int node = rows_s[row];
            float4 v = make_float4(0.f, 0.f, 0.f, 0.f);
            if (node >= 0)
                v = *reinterpret_cast<const float4*>(srcp + (size_t)node * CIN + kl + f4 * 4);
            __nv_bfloat16 hx = __float2bfloat16_rn(v.x), hy = __float2bfloat16_rn(v.y);
            __nv_bfloat16 hz = __float2bfloat16_rn(v.z), hw = __float2bfloat16_rn(v.w);
            __nv_bfloat162 h0 = __nv_bfloat162(hx, hy), h1 = __nv_bfloat162(hz, hw);
            __nv_bfloat162 l0 = __floats2bfloat162_rn(v.x - __bfloat162float(hx),
                                                      v.y - __bfloat162float(hy));
            __nv_bfloat162 l1 = __floats2bfloat162_rn(v.z - __bfloat162float(hz),
                                                      v.w - __bfloat162float(hw));
            uint32_t off = (uint32_t)(row * 128) + (uint32_t)((f4 * 8) ^ ((row & 7) << 4));
            *reinterpret_cast<uint2*>(smA_hi + off) =
                make_uint2(*reinterpret_cast<uint32_t*>(&h0), *reinterpret_cast<uint32_t*>(&h1));
            *reinterpret_cast<uint2*>(smA_lo + off) =
                make_uint2(*reinterpret_cast<uint32_t*>(&l0), *reinterpret_cast<uint32_t*>(&l1));
        }
        // ---- B tile: 64 n x 64 k bf16 (pre-split K-major), swizzled ----
#pragma unroll
        for (int it = 0; it < 2; it++) {
            int idx = it * 256 + tid;
            int n = idx >> 3, u = idx & 7;
            size_t so = ((size_t)(d * COUT + n0g + n)) * K + c * 64 + u * 8;
            uint32_t off = (uint32_t)(n * 128) + (uint32_t)((u * 16) ^ ((n & 7) << 4));
            *reinterpret_cast<uint4*>(smB_hi + off) = *reinterpret_cast<const uint4*>(Whi + so);
            *reinterpret_cast<uint4*>(smB_lo + off) = *reinterpret_cast<const uint4*>(Wlo + so);
        }
        __syncthreads();

        // ---- compute: 4 k-steps of 16 ----
#pragma unroll
        for (int kk = 0; kk < 4; kk++) {
            uint32_t a_hi[2][4], a_lo[2][4], b_hi[4][2], b_lo[4][2];
            const int mrow = wm * 32 + (lane & 15);
            const int kseg = lane >> 4;
#pragma unroll
            for (int t = 0; t < 2; t++) {
                int row = mrow + t * 16;
                uint32_t off = (uint32_t)(row * 128) +
                               (uint32_t)((kk * 32 + kseg * 16) ^ ((row & 7) << 4));
                ldsm_x4(a_hi[t], sA_hi + off);
                ldsm_x4(a_lo[t], sA_lo + off);
            }
            const int nlane = wn * 32 + (lane & 7);
            const int bseg  = (lane >> 3) & 1;
#pragma unroll
            for (int u = 0; u < 4; u++) {
                int n = nlane + u * 8;
                uint32_t off = (uint32_t)(n * 128) +
                               (uint32_t)((kk * 32 + bseg * 16) ^ ((n & 7) << 4));
                ldsm_x2(b_hi[u], sB_hi + off);
                ldsm_x2(b_lo[u], sB_lo + off);
            }
#pragma unroll
            for (int t = 0; t < 2; t++)
#pragma unroll
                for (int u = 0; u < 4; u++) {
                    mma_16816(acc[t][u], a_hi[t], b_hi[u]);
                    mma_16816(acc[t][u], a_hi[t], b_lo[u]);
                    mma_16816(acc[t][u], a_lo[t], b_hi[u]);
                }
        }
    }

    // ---- epilogue: bias + scatter rows ----
#pragma unroll
    for (int t = 0; t < 2; t++) {
        int r0 = wm * 32 + t * 16 + (lane >> 2);
#pragma unroll
        for (int u = 0; u < 4; u++) {
            int col = n0g + wn * 32 + u * 8 + (lane & 3) * 2;
            float2 bv = *reinterpret_cast<const float2*>(bl + d * COUT + col);
            int node0 = rows_s[r0];
            if (node0 >= 0) {
                float2 o = make_float2(acc[t][u][0] + bv.x, acc[t][u][1] + bv.y);
                *reinterpret_cast<float2*>(out + (size_t)node0 * COUT + col) = o;
            }
            int node1 = rows_s[r0 + 8];
            if (node1 >= 0) {
                float2 o = make_float2(acc[t][u][2] + bv.x, acc[t][u][3] + bv.y);
                *reinterpret_cast<float2*>(out + (size_t)node1 * COUT + col) = o;
            }
        }
    }
}

// ---------------- global add pool over batch ----------------
__global__ void k_pool(const int* __restrict__ batch) {
    int t = blockIdx.x * 256 + threadIdx.x;
    int i = t >> 6;
    int f = (t & 63) * 4;
    if (i >= N_NODES) return;
    float4 v = *reinterpret_cast<const float4*>(g_h3 + (size_t)i * 256 + f);
    red_add_v4(g_pool + (size_t)batch[i] * 256 + f, v);
}

// ---------------- final: concat @ Wf + bf, softmax ----------------
__global__ void k_final(const int* __restrict__ batch,
                        const float* __restrict__ Wf, const float* __restrict__ bf,
                        float* __restrict__ out) {
    int gt   = blockIdx.x * 256 + threadIdx.x;
    int node = gt >> 5;
    int lane = gt & 31;
    if (node >= N_NODES) return;

    float a0 = 0.f, a1 = 0.f;
    const int g = batch[node];
#pragma unroll 4
    for (int k = lane; k < 128; k += 32) {
        float v = g_h0[(size_t)node * 128 + k];
        float2 w = *reinterpret_cast<const float2*>(Wf + 2 * (0 + k));
        a0 += v * w.x; a1 += v * w.y;
    }
#pragma unroll 4
    for (int k = lane; k < 128; k += 32) {
        float v = g_h1[(size_t)node * 128 + k];
        float2 w = *reinterpret_cast<const float2*>(Wf + 2 * (128 + k));
        a0 += v * w.x; a1 += v * w.y;
    }
#pragma unroll 8
    for (int k = lane; k < 256; k += 32) {
        float v = g_h2[(size_t)node * 256 + k];
        float2 w = *reinterpret_cast<const float2*>(Wf + 2 * (256 + k));
        a0 += v * w.x; a1 += v * w.y;
    }
#pragma unroll 8
    for (int k = lane; k < 256; k += 32) {
        float v = g_h3[(size_t)node * 256 + k];
        float2 w = *reinterpret_cast<const float2*>(Wf + 2 * (512 + k));
        a0 += v * w.x; a1 += v * w.y;
    }
#pragma unroll 8
    for (int k = lane; k < 256; k += 32) {
        float v = g_pool[(size_t)g * 256 + k];
        float2 w = *reinterpret_cast<const float2*>(Wf + 2 * (768 + k));
        a0 += v * w.x; a1 += v * w.y;
    }
#pragma unroll
    for (int o = 16; o > 0; o >>= 1) {
        a0 += __shfl_xor_sync(0xFFFFFFFFu, a0, o);
        a1 += __shfl_xor_sync(0xFFFFFFFFu, a1, o);
    }
    if (lane == 0) {
        a0 += bf[0]; a1 += bf[1];
        float m  = fmaxf(a0, a1);
        float e0 = expf(a0 - m), e1 = expf(a1 - m);
        float s  = e0 + e1;
        out[(size_t)node * 2 + 0] = e0 / s;
        out[(size_t)node * 2 + 1] = e1 / s;
    }
}

// ---------------- launch ----------------
extern "C" void kernel_launch(void* const* d_in, const int* in_sizes, int n_in,
                              void* d_out, int out_size) {
    (void)in_sizes; (void)n_in; (void)out_size;
    const float* x     = (const float*)d_in[0];
    const int*   ei    = (const int*)d_in[1];
    const int*   batch = (const int*)d_in[2];
    const float* Wl0 = (const float*)d_in[3];
    const float* bl0 = (const float*)d_in[4];
    const float* Wr0 = (const float*)d_in[5];
    const float* Wl1 = (const float*)d_in[6];
    const float* bl1 = (const float*)d_in[7];
    const float* Wr1 = (const float*)d_in[8];
    const float* Wl2 = (const float*)d_in[9];
    const float* bl2 = (const float*)d_in[10];
    const float* Wr2 = (const float*)d_in[11];
    const float* Wl3 = (const float*)d_in[12];
    const float* bl3 = (const float*)d_in[13];
    const float* Wr3 = (const float*)d_in[14];
    const float* Wf  = (const float*)d_in[15];
    const float* bf  = (const float*)d_in[16];
    float* out = (float*)d_out;

    const int* src = ei;
    const int* dst = ei + N_EDGES;

    float *h0, *h1, *h2, *h3;
    __nv_bfloat16 *whi, *wlo;
    cudaGetSymbolAddress((void**)&h0, g_h0);
    cudaGetSymbolAddress((void**)&h1, g_h1);
    cudaGetSymbolAddress((void**)&h2, g_h2);
    cudaGetSymbolAddress((void**)&h3, g_h3);
    cudaGetSymbolAddress((void**)&whi, g_whi);
    cudaGetSymbolAddress((void**)&wlo, g_wlo);

    const int SMEM = 49152;
    cudaFuncSetAttribute(mf_gemm_mma<64, 128>,  cudaFuncAttributeMaxDynamicSharedMemorySize, SMEM);
    cudaFuncSetAttribute(mf_gemm_mma<128, 128>, cudaFuncAttributeMaxDynamicSharedMemorySize, SMEM);
    cudaFuncSetAttribute(mf_gemm_mma<128, 256>, cudaFuncAttributeMaxDynamicSharedMemorySize, SMEM);
    cudaFuncSetAttribute(mf_gemm_mma<256, 256>, cudaFuncAttributeMaxDynamicSharedMemorySize, SMEM);

    const int NB_N = (N_NODES + 255) / 256;
    const int NB_E = (N_EDGES + 255) / 256;
    const int T128 = (N_NODES + 127) / 128;  // 1563

    // degree + buckets
    k_zero_deg_meta<<<NB_N, 256>>>();
    k_deg<<<NB_E, 256>>>(dst);
    k_bcount<<<NB_N, 256>>>();
    k_offsets<<<1, 1>>>();
    k_fill<<<NB_N, 256>>>();

    // weight prep (split + transpose)
    k_prep_w<64, 128><<<(6 * 128 * 128 + 255) / 256, 256>>>(Wl0, Wr0, whi + WOFF0, wlo + WOFF0);
    k_prep_w<128, 128><<<(6 * 256 * 128 + 255) / 256, 256>>>(Wl1, Wr1, whi + WOFF1, wlo + WOFF1);
    k_prep_w<128, 256><<<(6 * 256 * 256 + 255) / 256, 256>>>(Wl2, Wr2, whi + WOFF2, wlo + WOFF2);
    k_prep_w<256, 256><<<(6 * 512 * 256 + 255) / 256, 256>>>(Wl3, Wr3, whi + WOFF3, wlo + WOFF3);

    // layer 0: CIN=64 -> 128
    k_zero_msg<<<(N_NODES * 16 + 255) / 256, 256>>>(N_NODES * 16);
    k_scatter<64><<<(N_EDGES * 16 + 255) / 256, 256>>>(x, src, dst);
    mf_gemm_mma<64, 128><<<dim3(T128 * 2, 6), 256, SMEM>>>(x, whi + WOFF0, wlo + WOFF0, bl0, h0);

    // layer 1: 128 -> 128
    k_zero_msg<<<(N_NODES * 32 + 255) / 256, 256>>>(N_NODES * 32);
    k_scatter<128><<<(N_EDGES * 32 + 255) / 256, 256>>>(h0, src, dst);
    mf_gemm_mma<128, 128><<<dim3(T128 * 2, 6), 256, SMEM>>>(h0, whi + WOFF1, wlo + WOFF1, bl1, h1);

    // layer 2: 128 -> 256
    k_zero_msg<<<(N_NODES * 32 + 255) / 256, 256>>>(N_NODES * 32);
    k_scatter<128><<<(N_EDGES * 32 + 255) / 256, 256>>>(h1, src, dst);
    mf_gemm_mma<128, 256><<<dim3(T128 * 4, 6), 256, SMEM>>>(h1, whi + WOFF2, wlo + WOFF2, bl2, h2);

    // layer 3: 256 -> 256
    k_zero_msg<<<(N_NODES * 64 + 255) / 256, 256>>>(N_NODES * 64);
    k_scatter<256><<<(N_EDGES * 64 + 255) / 256, 256>>>(h2, src, dst);
    mf_gemm_mma<256, 256><<<dim3(T128 * 4, 6), 256, SMEM>>>(h2, whi + WOFF3, wlo + WOFF3, bl3, h3);

    // pool + final
    k_zero_pool<<<(N_GRAPHS * 64 + 255) / 256, 256>>>();
    k_pool<<<(N_NODES * 64 + 255) / 256, 256>>>(batch);
    k_final<<<(N_NODES * 32 + 255) / 256, 256>>>(batch, Wf, bf, out);
}

// round 5
// speedup vs baseline: 2.0279x; 1.6464x over previous
#include <cuda_runtime.h>
#include <cuda_bf16.h>
#include <cstdint>

#define N_NODES  200000
#define N_EDGES  800000
#define N_GRAPHS 4096
#define MAXDEG   5
#define NBLK_SCAN 782   // ceil(N_NODES/256)

// ---------------- scratch (static __device__, no allocs) ----------------
__device__ float g_h0[N_NODES * 128];
__device__ float g_h1[N_NODES * 128];
__device__ float g_h2[N_NODES * 256];
__device__ float g_h3[N_NODES * 256];
__device__ float g_pool[N_GRAPHS * 256];
__device__ __nv_bfloat16 g_msg_hi[N_NODES * 256];
__device__ __nv_bfloat16 g_msg_lo[N_NODES * 256];
__device__ __nv_bfloat16 g_sa_hi[N_NODES * 256];
__device__ __nv_bfloat16 g_sa_lo[N_NODES * 256];
__device__ __nv_bfloat16 g_sb_hi[N_NODES * 256];
__device__ __nv_bfloat16 g_sb_lo[N_NODES * 256];
__device__ int   g_deg[N_NODES];
__device__ int   g_cur[N_NODES];
__device__ int   g_perm[N_NODES];
__device__ int   g_csr_off[N_NODES + 1];
__device__ int   g_csr[N_EDGES];
__device__ int   g_bsum[1024];
__device__ int   g_bpre[1024];
// [0..5] counts, [8..13] offsets, [16..21] cursors
__device__ int   g_meta[64];

// split-bf16 transposed weights: [d][n][k] K-major (k spans 2*CIN: Wl then Wr)
#define WOFF0 0
#define WOFF1 98304
#define WOFF2 294912
#define WOFF3 688128
#define WTOT  1474560
__device__ __nv_bfloat16 g_whi[WTOT];
__device__ __nv_bfloat16 g_wlo[WTOT];

// ---------------- helpers (portable PTX only) ----------------
__device__ __forceinline__ uint32_t smem_u32(const void* p) {
    uint32_t a;
    asm("{ .reg .u64 t; cvta.to.shared.u64 t, %1; cvt.u32.u64 %0, t; }" : "=r"(a) : "l"(p));
    return a;
}
__device__ __forceinline__ void red_add_v4(float* addr, float4 v) {
    asm volatile("red.global.add.v4.f32 [%0], {%1,%2,%3,%4};"
                 :: "l"(addr), "f"(v.x), "f"(v.y), "f"(v.z), "f"(v.w) : "memory");
}
__device__ __forceinline__ void ldsm_x4(uint32_t* r, uint32_t addr) {
    asm volatile("ldmatrix.sync.aligned.m8n8.x4.shared.b16 {%0,%1,%2,%3}, [%4];"
                 : "=r"(r[0]), "=r"(r[1]), "=r"(r[2]), "=r"(r[3]) : "r"(addr));
}
__device__ __forceinline__ void ldsm_x2(uint32_t* r, uint32_t addr) {
    asm volatile("ldmatrix.sync.aligned.m8n8.x2.shared.b16 {%0,%1}, [%2];"
                 : "=r"(r[0]), "=r"(r[1]) : "r"(addr));
}
__device__ __forceinline__ void mma_16816(float* c, const uint32_t* a, const uint32_t* b) {
    asm volatile("mma.sync.aligned.m16n8k16.row.col.f32.bf16.bf16.f32 "
                 "{%0,%1,%2,%3}, {%4,%5,%6,%7}, {%8,%9}, {%0,%1,%2,%3};"
                 : "+f"(c[0]), "+f"(c[1]), "+f"(c[2]), "+f"(c[3])
                 : "r"(a[0]), "r"(a[1]), "r"(a[2]), "r"(a[3]), "r"(b[0]), "r"(b[1]));
}
__device__ __forceinline__ void cp_async16(uint32_t s, const void* g, uint32_t sz) {
    asm volatile("cp.async.cg.shared.global [%0], [%1], 16, %2;"
                 :: "r"(s), "l"(g), "r"(sz) : "memory");
}
__device__ __forceinline__ uint32_t pack_hi(float x, float y, float& lx, float& ly) {
    __nv_bfloat16 h0 = __float2bfloat16_rn(x), h1 = __float2bfloat16_rn(y);
    lx = x - __bfloat162float(h0);
    ly = y - __bfloat162float(h1);
    __nv_bfloat162 hp(h0, h1);
    return *reinterpret_cast<uint32_t*>(&hp);
}
__device__ __forceinline__ uint32_t pack_bf2(float x, float y) {
    __nv_bfloat162 p = __floats2bfloat162_rn(x, y);
    return *reinterpret_cast<uint32_t*>(&p);
}

// ---------------- degree / scan / csr / buckets ----------------
__global__ void k_zero_deg() {
    int i = blockIdx.x * 256 + threadIdx.x;
    if (i < N_NODES) { g_deg[i] = 0; g_cur[i] = 0; }
    if (i < 64) g_meta[i] = 0;
}
__global__ void k_deg(const int* __restrict__ dst) {
    int e = blockIdx.x * 256 + threadIdx.x;
    if (e < N_EDGES) atomicAdd(&g_deg[dst[e]], 1);
}
__global__ void k_scan1() {
    __shared__ int s[256];
    int b = blockIdx.x, t = threadIdx.x, i = b * 256 + t;
    int v = (i < N_NODES) ? g_deg[i] : 0;
    s[t] = v;
    __syncthreads();
#pragma unroll
    for (int o = 1; o < 256; o <<= 1) {
        int u = (t >= o) ? s[t - o] : 0;
        __syncthreads();
        s[t] += u;
        __syncthreads();
    }
    if (i < N_NODES) g_csr_off[i] = s[t] - v;
    if (t == 255) g_bsum[b] = s[255];
}
__global__ void k_scan2() {
    __shared__ int s[1024];
    int t = threadIdx.x;
    int v = (t < NBLK_SCAN) ? g_bsum[t] : 0;
    s[t] = v;
    __syncthreads();
#pragma unroll
    for (int o = 1; o < 1024; o <<= 1) {
        int u = (t >= o) ? s[t - o] : 0;
        __syncthreads();
        s[t] += u;
        __syncthreads();
    }
    if (t < NBLK_SCAN) g_bpre[t] = s[t] - v;
}
__global__ void k_scan3() {
    int i = blockIdx.x * 256 + threadIdx.x;
    if (i < N_NODES) g_csr_off[i] += g_bpre[i >> 8];
    if (i == 0) g_csr_off[N_NODES] = N_EDGES;
}
__global__ void k_csr_fill(const int* __restrict__ src, const int* __restrict__ dst) {
    int e = blockIdx.x * 256 + threadIdx.x;
    if (e < N_EDGES) {
        int d = dst[e];
        int p = atomicAdd(&g_cur[d], 1);
        g_csr[g_csr_off[d] + p] = src[e];
    }
}
__global__ void k_bcount() {
    int i = blockIdx.x * 256 + threadIdx.x;
    if (i < N_NODES) atomicAdd(&g_meta[min(g_deg[i], MAXDEG)], 1);
}
__global__ void k_offsets() {
    int s = 0;
    for (int d = 0; d <= MAXDEG; d++) { g_meta[8 + d] = s; s += g_meta[d]; }
}
__global__ void k_fill() {
    int i = blockIdx.x * 256 + threadIdx.x;
    if (i < N_NODES) {
        int d = min(g_deg[i], MAXDEG);
        int p = atomicAdd(&g_meta[16 + d], 1);
        g_perm[g_meta[8 + d] + p] = i;
    }
}

// ---------------- CSR aggregation -> split bf16 msg ----------------
template <int CIN>
__global__ void k_agg(const float* __restrict__ h,
                      __nv_bfloat16* __restrict__ mh, __nv_bfloat16* __restrict__ ml) {
    const int PER = CIN / 8;
    int t = blockIdx.x * 256 + threadIdx.x;
    int node = t / PER, g = t % PER;
    if (node >= N_NODES) return;
    int j0 = g_csr_off[node], j1 = g_csr_off[node + 1];
    float a[8];
#pragma unroll
    for (int i = 0; i < 8; i++) a[i] = 0.f;
    for (int j = j0; j < j1; j++) {
        int s = g_csr[j];
        const float4* p = reinterpret_cast<const float4*>(h + (size_t)s * CIN + g * 8);
        float4 v0 = p[0], v1 = p[1];
        a[0] += v0.x; a[1] += v0.y; a[2] += v0.z; a[3] += v0.w;
        a[4] += v1.x; a[5] += v1.y; a[6] += v1.z; a[7] += v1.w;
    }
    uint4 hw, lw;
    float l0, l1;
    hw.x = pack_hi(a[0], a[1], l0, l1); lw.x = pack_bf2(l0, l1);
    hw.y = pack_hi(a[2], a[3], l0, l1); lw.y = pack_bf2(l0, l1);
    hw.z = pack_hi(a[4], a[5], l0, l1); lw.z = pack_bf2(l0, l1);
    hw.w = pack_hi(a[6], a[7], l0, l1); lw.w = pack_bf2(l0, l1);
    *reinterpret_cast<uint4*>(mh + (size_t)node * CIN + g * 8) = hw;
    *reinterpret_cast<uint4*>(ml + (size_t)node * CIN + g * 8) = lw;
}

// ---------------- x split ----------------
__global__ void k_split_x(const float* __restrict__ x,
                          __nv_bfloat16* __restrict__ xh, __nv_bfloat16* __restrict__ xl) {
    int t = blockIdx.x * 256 + threadIdx.x;   // N_NODES*8 threads (8 floats each)
    if (t >= N_NODES * 8) return;
    const float4* p = reinterpret_cast<const float4*>(x + (size_t)t * 8);
    float4 v0 = p[0], v1 = p[1];
    uint4 hw, lw;
    float l0, l1;
    hw.x = pack_hi(v0.x, v0.y, l0, l1); lw.x = pack_bf2(l0, l1);
    hw.y = pack_hi(v0.z, v0.w, l0, l1); lw.y = pack_bf2(l0, l1);
    hw.z = pack_hi(v1.x, v1.y, l0, l1); lw.z = pack_bf2(l0, l1);
    hw.w = pack_hi(v1.z, v1.w, l0, l1); lw.w = pack_bf2(l0, l1);
    *reinterpret_cast<uint4*>(xh + (size_t)t * 8) = hw;
    *reinterpret_cast<uint4*>(xl + (size_t)t * 8) = lw;
}

// ---------------- weight prep: transpose + bf16 hi/lo split ----------------
template <int CIN, int COUT>
__global__ void k_prep_w(const float* __restrict__ Wl, const float* __restrict__ Wr,
                         __nv_bfloat16* __restrict__ Whi, __nv_bfloat16* __restrict__ Wlo) {
    const int K = 2 * CIN;
    int t = blockIdx.x * 256 + threadIdx.x;
    if (t >= 6 * K * COUT) return;
    int n = t % COUT;
    int k = (t / COUT) % K;
    int d = t / (COUT * K);
    float v = (k < CIN) ? Wl[((size_t)d * CIN + k) * COUT + n]
                        : Wr[((size_t)d * CIN + (k - CIN)) * COUT + n];
    __nv_bfloat16 hi = __float2bfloat16_rn(v);
    float lo = v - __bfloat162float(hi);
    size_t o = ((size_t)(d * COUT + n)) * K + k;
    Whi[o] = hi;
    Wlo[o] = __float2bfloat16_rn(lo);
}

// ---------------- pipelined mma.sync bucketed GEMM (split-bf16, 3-term) ----------------
// Tile 128(M) x 128(N), K chunk 64, cp.async double-buffered.
// Warps: 4(M) x 2(N); warp tile 32 x 64.
template <int CIN, int COUT, bool WS>
__global__ __launch_bounds__(256, 1)
void mf_gemm(const __nv_bfloat16* __restrict__ hp_hi, const __nv_bfloat16* __restrict__ hp_lo,
             const __nv_bfloat16* __restrict__ Whi, const __nv_bfloat16* __restrict__ Wlo,
             const float* __restrict__ bl, float* __restrict__ hout,
             __nv_bfloat16* __restrict__ nx_hi, __nv_bfloat16* __restrict__ nx_lo) {
    constexpr int K     = 2 * CIN;
    constexpr int NCH   = K / 64;
    constexpr int NSLAB = COUT / 128;
    constexpr uint32_t STG = 65536;

    extern __shared__ char smem[];
    __shared__ int rows_s[128];

    const int slab = blockIdx.x % NSLAB;
    const int tile = blockIdx.x / NSLAB;
    const int d    = blockIdx.y;
    const int M    = g_meta[d];
    const int m0   = tile * 128;
    if (m0 >= M) return;
    const int base = g_meta[8 + d];
    const int n0g  = slab * 128;
    const int tid  = threadIdx.x;
    const int lane = tid & 31, wid = tid >> 5;
    const int wm   = wid & 3, wn = wid >> 2;

    if (tid < 128) {
        int mi = m0 + tid;
        rows_s[tid] = (mi < M) ? g_perm[base + mi] : -1;
    }
    __syncthreads();

    const uint32_t sb = smem_u32(smem);

    auto load_chunk = [&](int c, int buf) {
        const __nv_bfloat16 *ah, *al;
        int kl;
        if (c * 64 < CIN) { ah = g_msg_hi; al = g_msg_lo; kl = c * 64; }
        else              { ah = hp_hi;    al = hp_lo;    kl = c * 64 - CIN; }
        uint32_t s0 = sb + buf * STG;
#pragma unroll
        for (int it = 0; it < 4; it++) {
            int idx = it * 256 + tid;
            int row = idx >> 3, seg = idx & 7;
            int node = rows_s[row];
            uint32_t doff = (uint32_t)(row * 128) + (uint32_t)((seg * 16) ^ ((row & 7) << 4));
            size_t go = (size_t)(node < 0 ? 0 : node) * CIN + kl + seg * 8;
            uint32_t sz = (node < 0) ? 0u : 16u;
            cp_async16(s0 + doff, ah + go, sz);
            cp_async16(s0 + 16384 + doff, al + go, sz);
        }
#pragma unroll
        for (int it = 0; it < 4; it++) {
            int idx = it * 256 + tid;
            int n = idx >> 3, seg = idx & 7;
            uint32_t doff = (uint32_t)(n * 128) + (uint32_t)((seg * 16) ^ ((n & 7) << 4));
            size_t go = ((size_t)(d * COUT + n0g + n)) * K + c * 64 + seg * 8;
            cp_async16(s0 + 32768 + doff, Whi + go, 16);
            cp_async16(s0 + 49152 + doff, Wlo + go, 16);
        }
        asm volatile("cp.async.commit_group;" ::: "memory");
    };

    float acc[2][8][4];
#pragma unroll
    for (int t = 0; t < 2; t++)
#pragma unroll
        for (int u = 0; u < 8; u++)
#pragma unroll
            for (int i = 0; i < 4; i++) acc[t][u][i] = 0.f;

    load_chunk(0, 0);

    for (int c = 0; c < NCH; c++) {
        if (c + 1 < NCH) {
            load_chunk(c + 1, (c + 1) & 1);
            asm volatile("cp.async.wait_group 1;" ::: "memory");
        } else {
            asm volatile("cp.async.wait_group 0;" ::: "memory");
        }
        __syncthreads();

        uint32_t s0 = sb + (uint32_t)(c & 1) * STG;
        uint32_t sAh = s0, sAl = s0 + 16384, sBh = s0 + 32768, sBl = s0 + 49152;
#pragma unroll
        for (int kk = 0; kk < 4; kk++) {
            uint32_t a_hi[2][4], a_lo[2][4];
            const int mrow = wm * 32 + (lane & 15);
            const int kseg = lane >> 4;
#pragma unroll
            for (int t = 0; t < 2; t++) {
                int row = mrow + t * 16;
                uint32_t off = (uint32_t)(row * 128) +
                               (uint32_t)((kk * 32 + kseg * 16) ^ ((row & 7) << 4));
                ldsm_x4(a_hi[t], sAh + off);
                ldsm_x4(a_lo[t], sAl + off);
            }
            const int nlane = wn * 64 + (lane & 7);
            const int bseg  = (lane >> 3) & 1;
            uint32_t b_hi[8][2], b_lo[8][2];
#pragma unroll
            for (int u = 0; u < 8; u++) {
                int n = nlane + u * 8;
                uint32_t off = (uint32_t)(n * 128) +
                               (uint32_t)((kk * 32 + bseg * 16) ^ ((n & 7) << 4));
                ldsm_x2(b_hi[u], sBh + off);
                ldsm_x2(b_lo[u], sBl + off);
            }
#pragma unroll
            for (int t = 0; t < 2; t++)
#pragma unroll
                for (int u = 0; u < 8; u++) {
                    mma_16816(acc[t][u], a_hi[t], b_hi[u]);
                    mma_16816(acc[t][u], a_hi[t], b_lo[u]);
                    mma_16816(acc[t][u], a_lo[t], b_hi[u]);
                }
        }
        __syncthreads();
    }

    // ---- epilogue: bias + fp32 out + split bf16 out ----
#pragma unroll
    for (int t = 0; t < 2; t++) {
        int r0 = wm * 32 + t * 16 + (lane >> 2);
#pragma unroll
        for (int u = 0; u < 8; u++) {
            int col = n0g + wn * 64 + u * 8 + (lane & 3) * 2;
            float2 bv = *reinterpret_cast<const float2*>(bl + d * COUT + col);
            int nd0 = rows_s[r0];
            if (nd0 >= 0) {
                float ox = acc[t][u][0] + bv.x, oy = acc[t][u][1] + bv.y;
                *reinterpret_cast<float2*>(hout + (size_t)nd0 * COUT + col) = make_float2(ox, oy);
                if (WS) {
                    float lx, ly;
                    uint32_t hw = pack_hi(ox, oy, lx, ly);
                    *reinterpret_cast<uint32_t*>(nx_hi + (size_t)nd0 * COUT + col) = hw;
                    *reinterpret_cast<uint32_t*>(nx_lo + (size_t)nd0 * COUT + col) = pack_bf2(lx, ly);
                }
            }
            int nd1 = rows_s[r0 + 8];
            if (nd1 >= 0) {
                float ox = acc[t][u][2] + bv.x, oy = acc[t][u][3] + bv.y;
                *reinterpret_cast<float2*>(hout + (size_t)nd1 * COUT + col) = make_float2(ox, oy);
                if (WS) {
                    float lx, ly;
                    uint32_t hw = pack_hi(ox, oy, lx, ly);
                    *reinterpret_cast<uint32_t*>(nx_hi + (size_t)nd1 * COUT + col) = hw;
                    *reinterpret_cast<uint32_t*>(nx_lo + (size_t)nd1 * COUT + col) = pack_bf2(lx, ly);
                }
            }
        }
    }
}

// ---------------- pool + final ----------------
__global__ void k_zero_pool() {
    int i = blockIdx.x * 256 + threadIdx.x;
    if (i < N_GRAPHS * 256 / 4)
        reinterpret_cast<float4*>(g_pool)[i] = make_float4(0.f, 0.f, 0.f, 0.f);
}
__global__ void k_pool(const int* __restrict__ batch) {
    int t = blockIdx.x * 256 + threadIdx.x;
    int i = t >> 6;
    int f = (t & 63) * 4;
    if (i >= N_NODES) return;
    float4 v = *reinterpret_cast<const float4*>(g_h3 + (size_t)i * 256 + f);
    red_add_v4(g_pool + (size_t)batch[i] * 256 + f, v);
}
__global__ void k_final(const int* __restrict__ batch,
                        const float* __restrict__ Wf, const float* __restrict__ bf,
                        float* __restrict__ out) {
    int gt   = blockIdx.x * 256 + threadIdx.x;
    int node = gt >> 5;
    int lane = gt & 31;
    if (node >= N_NODES) return;

    float a0 = 0.f, a1 = 0.f;
    const int g = batch[node];
#pragma unroll 4
    for (int k = lane; k < 128; k += 32) {
        float v = g_h0[(size_t)node * 128 + k];
        float2 w = *reinterpret_cast<const float2*>(Wf + 2 * (0 + k));
        a0 += v * w.x; a1 += v * w.y;
    }
#pragma unroll 4
    for (int k = lane; k < 128; k += 32) {
        float v = g_h1[(size_t)node * 128 + k];
        float2 w = *reinterpret_cast<const float2*>(Wf + 2 * (128 + k));
        a0 += v * w.x; a1 += v * w.y;
    }
#pragma unroll 8
    for (int k = lane; k < 256; k += 32) {
        float v = g_h2[(size_t)node * 256 + k];
        float2 w = *reinterpret_cast<const float2*>(Wf + 2 * (256 + k));
        a0 += v * w.x; a1 += v * w.y;
    }
#pragma unroll 8
    for (int k = lane; k < 256; k += 32) {
        float v = g_h3[(size_t)node * 256 + k];
        float2 w = *reinterpret_cast<const float2*>(Wf + 2 * (512 + k));
        a0 += v * w.x; a1 += v * w.y;
    }
#pragma unroll 8
    for (int k = lane; k < 256; k += 32) {
        float v = g_pool[(size_t)g * 256 + k];
        float2 w = *reinterpret_cast<const float2*>(Wf + 2 * (768 + k));
        a0 += v * w.x; a1 += v * w.y;
    }
#pragma unroll
    for (int o = 16; o > 0; o >>= 1) {
        a0 += __shfl_xor_sync(0xFFFFFFFFu, a0, o);
        a1 += __shfl_xor_sync(0xFFFFFFFFu, a1, o);
    }
    if (lane == 0) {
        a0 += bf[0]; a1 += bf[1];
        float m  = fmaxf(a0, a1);
        float e0 = expf(a0 - m), e1 = expf(a1 - m);
        float s  = e0 + e1;
        out[(size_t)node * 2 + 0] = e0 / s;
        out[(size_t)node * 2 + 1] = e1 / s;
    }
}

// ---------------- launch ----------------
extern "C" void kernel_launch(void* const* d_in, const int* in_sizes, int n_in,
                              void* d_out, int out_size) {
    (void)in_sizes; (void)n_in; (void)out_size;
    const float* x     = (const float*)d_in[0];
    const int*   ei    = (const int*)d_in[1];
    const int*   batch = (const int*)d_in[2];
    const float* Wl0 = (const float*)d_in[3];
    const float* bl0 = (const float*)d_in[4];
    const float* Wr0 = (const float*)d_in[5];
    const float* Wl1 = (const float*)d_in[6];
    const float* bl1 = (const float*)d_in[7];
    const float* Wr1 = (const float*)d_in[8];
    const float* Wl2 = (const float*)d_in[9];
    const float* bl2 = (const float*)d_in[10];
    const float* Wr2 = (const float*)d_in[11];
    const float* Wl3 = (const float*)d_in[12];
    const float* bl3 = (const float*)d_in[13];
    const float* Wr3 = (const float*)d_in[14];
    const float* Wf  = (const float*)d_in[15];
    const float* bf  = (const float*)d_in[16];
    float* out = (float*)d_out;

    const int* src = ei;
    const int* dst = ei + N_EDGES;

    float *h0, *h1, *h2, *h3;
    __nv_bfloat16 *whi, *wlo, *sah, *sal, *sbh, *sbl, *mh, *ml;
    cudaGetSymbolAddress((void**)&h0, g_h0);
    cudaGetSymbolAddress((void**)&h1, g_h1);
    cudaGetSymbolAddress((void**)&h2, g_h2);
    cudaGetSymbolAddress((void**)&h3, g_h3);
    cudaGetSymbolAddress((void**)&whi, g_whi);
    cudaGetSymbolAddress((void**)&wlo, g_wlo);
    cudaGetSymbolAddress((void**)&sah, g_sa_hi);
    cudaGetSymbolAddress((void**)&sal, g_sa_lo);
    cudaGetSymbolAddress((void**)&sbh, g_sb_hi);
    cudaGetSymbolAddress((void**)&sbl, g_sb_lo);
    cudaGetSymbolAddress((void**)&mh, g_msg_hi);
    cudaGetSymbolAddress((void**)&ml, g_msg_lo);

    const int SMEM = 131072;
    cudaFuncSetAttribute(mf_gemm<64, 128, true>,   cudaFuncAttributeMaxDynamicSharedMemorySize, SMEM);
    cudaFuncSetAttribute(mf_gemm<128, 128, true>,  cudaFuncAttributeMaxDynamicSharedMemorySize, SMEM);
    cudaFuncSetAttribute(mf_gemm<128, 256, true>,  cudaFuncAttributeMaxDynamicSharedMemorySize, SMEM);
    cudaFuncSetAttribute(mf_gemm<256, 256, false>, cudaFuncAttributeMaxDynamicSharedMemorySize, SMEM);

    const int NB_N = (N_NODES + 255) / 256;
    const int NB_E = (N_EDGES + 255) / 256;
    const int T128 = (N_NODES + 127) / 128;  // 1563

    // degree + CSR + buckets
    k_zero_deg<<<NB_N, 256>>>();
    k_deg<<<NB_E, 256>>>(dst);
    k_scan1<<<NBLK_SCAN, 256>>>();
    k_scan2<<<1, 1024>>>();
    k_scan3<<<NB_N, 256>>>();
    k_csr_fill<<<NB_E, 256>>>(src, dst);
    k_bcount<<<NB_N, 256>>>();
    k_offsets<<<1, 1>>>();
    k_fill<<<NB_N, 256>>>();

    // weight prep + x split
    k_prep_w<64, 128><<<(6 * 128 * 128 + 255) / 256, 256>>>(Wl0, Wr0, whi + WOFF0, wlo + WOFF0);
    k_prep_w<128, 128><<<(6 * 256 * 128 + 255) / 256, 256>>>(Wl1, Wr1, whi + WOFF1, wlo + WOFF1);
    k_prep_w<128, 256><<<(6 * 256 * 256 + 255) / 256, 256>>>(Wl2, Wr2, whi + WOFF2, wlo + WOFF2);
    k_prep_w<256, 256><<<(6 * 512 * 256 + 255) / 256, 256>>>(Wl3, Wr3, whi + WOFF3, wlo + WOFF3);
    k_split_x<<<(N_NODES * 8 + 255) / 256, 256>>>(x, sah, sal);

    // layer 0: 64 -> 128   (A-right = x split in sa; writes h0 + split into sb)
    k_agg<64><<<(N_NODES * 8 + 255) / 256, 256>>>(x, mh, ml);
    mf_gemm<64, 128, true><<<dim3(T128, 6), 256, SMEM>>>(sah, sal, whi + WOFF0, wlo + WOFF0, bl0, h0, sbh, sbl);

    // layer 1: 128 -> 128  (A-right = sb; writes h1 + split into sa)
    k_agg<128><<<(N_NODES * 16 + 255) / 256, 256>>>(h0, mh, ml);
    mf_gemm<128, 128, true><<<dim3(T128, 6), 256, SMEM>>>(sbh, sbl, whi + WOFF1, wlo + WOFF1, bl1, h1, sah, sal);

    // layer 2: 128 -> 256  (A-right = sa; writes h2 + split into sb)
    k_agg<128><<<(N_NODES * 16 + 255) / 256, 256>>>(h1, mh, ml);
    mf_gemm<128, 256, true><<<dim3(T128 * 2, 6), 256, SMEM>>>(sah, sal, whi + WOFF2, wlo + WOFF2, bl2, h2, sbh, sbl);

    // layer 3: 256 -> 256  (A-right = sb; writes h3 only)
    k_agg<256><<<(N_NODES * 32 + 255) / 256, 256>>>(h2, mh, ml);
    mf_gemm<256, 256, false><<<dim3(T128 * 2, 6), 256, SMEM>>>(sbh, sbl, whi + WOFF3, wlo + WOFF3, bl3, h3, nullptr, nullptr);

    // pool + final
    k_zero_pool<<<(N_GRAPHS * 64 + 255) / 256, 256>>>();
    k_pool<<<(N_NODES * 64 + 255) / 256, 256>>>(batch);
    k_final<<<(N_NODES * 32 + 255) / 256, 256>>>(batch, Wf, bf, out);
}

// round 7
// speedup vs baseline: 2.2838x; 1.1262x over previous
#include <cuda_runtime.h>
#include <cuda_bf16.h>
#include <cstdint>

#define N_NODES  200000
#define N_EDGES  800000
#define N_GRAPHS 4096
#define MAXDEG   5
#define NBLK_SCAN 782   // ceil(N_NODES/256)

// ---------------- scratch (static __device__, no allocs) ----------------
__device__ float g_pool[N_GRAPHS * 256];
__device__ float g_logit[N_NODES * 2];
__device__ float g_glogit[N_GRAPHS * 2];
__device__ __nv_bfloat16 g_msg_hi[N_NODES * 256];
__device__ __nv_bfloat16 g_msg_lo[N_NODES * 256];
__device__ __nv_bfloat16 g_sa_hi[N_NODES * 256];
__device__ __nv_bfloat16 g_sa_lo[N_NODES * 256];
__device__ __nv_bfloat16 g_sb_hi[N_NODES * 256];
__device__ __nv_bfloat16 g_sb_lo[N_NODES * 256];
__device__ int   g_deg[N_NODES];
__device__ int   g_cur[N_NODES];
__device__ int   g_perm[N_NODES];
__device__ int   g_csr_off[N_NODES + 1];
__device__ int   g_csr[N_EDGES];
__device__ int   g_bsum[1024];
__device__ int   g_bpre[1024];
__device__ int   g_meta[64];

// split-bf16 transposed weights: [d][n][k] K-major (k spans 2*CIN: Wl then Wr)
#define WOFF0 0
#define WOFF1 98304
#define WOFF2 294912
#define WOFF3 688128
#define WTOT  1474560
__device__ __nv_bfloat16 g_whi[WTOT];
__device__ __nv_bfloat16 g_wlo[WTOT];

// ---------------- helpers (portable PTX only) ----------------
__device__ __forceinline__ uint32_t smem_u32(const void* p) {
    uint32_t a;
    asm("{ .reg .u64 t; cvta.to.shared.u64 t, %1; cvt.u32.u64 %0, t; }" : "=r"(a) : "l"(p));
    return a;
}
__device__ __forceinline__ void red_add_v4(float* addr, float4 v) {
    asm volatile("red.global.add.v4.f32 [%0], {%1,%2,%3,%4};"
                 :: "l"(addr), "f"(v.x), "f"(v.y), "f"(v.z), "f"(v.w) : "memory");
}
__device__ __forceinline__ void ldsm_x4(uint32_t* r, uint32_t addr) {
    asm volatile("ldmatrix.sync.aligned.m8n8.x4.shared.b16 {%0,%1,%2,%3}, [%4];"
                 : "=r"(r[0]), "=r"(r[1]), "=r"(r[2]), "=r"(r[3]) : "r"(addr));
}
__device__ __forceinline__ void ldsm_x2(uint32_t* r, uint32_t addr) {
    asm volatile("ldmatrix.sync.aligned.m8n8.x2.shared.b16 {%0,%1}, [%2];"
                 : "=r"(r[0]), "=r"(r[1]) : "r"(addr));
}
__device__ __forceinline__ void mma_16816(float* c, const uint32_t* a, const uint32_t* b) {
    asm volatile("mma.sync.aligned.m16n8k16.row.col.f32.bf16.bf16.f32 "
                 "{%0,%1,%2,%3}, {%4,%5,%6,%7}, {%8,%9}, {%0,%1,%2,%3};"
                 : "+f"(c[0]), "+f"(c[1]), "+f"(c[2]), "+f"(c[3])
                 : "r"(a[0]), "r"(a[1]), "r"(a[2]), "r"(a[3]), "r"(b[0]), "r"(b[1]));
}
__device__ __forceinline__ void cp_async16(uint32_t s, const void* g, uint32_t sz) {
    asm volatile("cp.async.cg.shared.global [%0], [%1], 16, %2;"
                 :: "r"(s), "l"(g), "r"(sz) : "memory");
}
__device__ __forceinline__ uint32_t pack_hi(float x, float y, float& lx, float& ly) {
    __nv_bfloat16 h0 = __float2bfloat16_rn(x), h1 = __float2bfloat16_rn(y);
    lx = x - __bfloat162float(h0);
    ly = y - __bfloat162float(h1);
    __nv_bfloat162 hp(h0, h1);
    return *reinterpret_cast<uint32_t*>(&hp);
}
__device__ __forceinline__ uint32_t pack_bf2(float x, float y) {
    __nv_bfloat162 p = __floats2bfloat162_rn(x, y);
    return *reinterpret_cast<uint32_t*>(&p);
}
__device__ __forceinline__ float2 upk(uint32_t u) {
    return __bfloat1622float2(*reinterpret_cast<__nv_bfloat162*>(&u));
}

// ---------------- degree / scan / csr / buckets ----------------
__global__ void k_zero_deg() {
    int i = blockIdx.x * 256 + threadIdx.x;
    if (i < N_NODES) {
        g_deg[i] = 0; g_cur[i] = 0;
        *reinterpret_cast<float2*>(g_logit + i * 2) = make_float2(0.f, 0.f);
    }
    if (i < 64) g_meta[i] = 0;
}
__global__ void k_deg(const int* __restrict__ dst) {
    int e = blockIdx.x * 256 + threadIdx.x;
    if (e < N_EDGES) atomicAdd(&g_deg[dst[e]], 1);
}
__global__ void k_scan1() {
    __shared__ int s[256];
    int b = blockIdx.x, t = threadIdx.x, i = b * 256 + t;
    int v = (i < N_NODES) ? g_deg[i] : 0;
    s[t] = v;
    __syncthreads();
#pragma unroll
    for (int o = 1; o < 256; o <<= 1) {
        int u = (t >= o) ? s[t - o] : 0;
        __syncthreads();
        s[t] += u;
        __syncthreads();
    }
    if (i < N_NODES) g_csr_off[i] = s[t] - v;
    if (t == 255) g_bsum[b] = s[255];
}
__global__ void k_scan2() {
    __shared__ int s[1024];
    int t = threadIdx.x;
    int v = (t < NBLK_SCAN) ? g_bsum[t] : 0;
    s[t] = v;
    __syncthreads();
#pragma unroll
    for (int o = 1; o < 1024; o <<= 1) {
        int u = (t >= o) ? s[t - o] : 0;
        __syncthreads();
        s[t] += u;
        __syncthreads();
    }
    if (t < NBLK_SCAN) g_bpre[t] = s[t] - v;
}
__global__ void k_scan3() {
    int i = blockIdx.x * 256 + threadIdx.x;
    if (i < N_NODES) g_csr_off[i] += g_bpre[i >> 8];
    if (i == 0) g_csr_off[N_NODES] = N_EDGES;
}
__global__ void k_csr_fill(const int* __restrict__ src, const int* __restrict__ dst) {
    int e = blockIdx.x * 256 + threadIdx.x;
    if (e < N_EDGES) {
        int d = dst[e];
        int p = atomicAdd(&g_cur[d], 1);
        g_csr[g_csr_off[d] + p] = src[e];
    }
}
__global__ void k_bcount() {
    int i = blockIdx.x * 256 + threadIdx.x;
    if (i < N_NODES) atomicAdd(&g_meta[min(g_deg[i], MAXDEG)], 1);
}
__global__ void k_offsets() {
    int s = 0;
    for (int d = 0; d <= MAXDEG; d++) { g_meta[8 + d] = s; s += g_meta[d]; }
}
__global__ void k_fill() {
    int i = blockIdx.x * 256 + threadIdx.x;
    if (i < N_NODES) {
        int d = min(g_deg[i], MAXDEG);
        int p = atomicAdd(&g_meta[16 + d], 1);
        g_perm[g_meta[8 + d] + p] = i;
    }
}

// ---------------- CSR aggregation (split input -> split msg) ----------------
template <int CIN>
__global__ void k_agg(const __nv_bfloat16* __restrict__ hh, const __nv_bfloat16* __restrict__ hl,
                      __nv_bfloat16* __restrict__ mh, __nv_bfloat16* __restrict__ ml) {
    const int PER = CIN / 8;
    int t = blockIdx.x * 256 + threadIdx.x;
    int node = t / PER, g = t % PER;
    if (node >= N_NODES) return;
    int j0 = g_csr_off[node], j1 = g_csr_off[node + 1];
    float a[8];
#pragma unroll
    for (int i = 0; i < 8; i++) a[i] = 0.f;
    for (int j = j0; j < j1; j++) {
        int s = g_csr[j];
        uint4 hv = *reinterpret_cast<const uint4*>(hh + (size_t)s * CIN + g * 8);
        uint4 lv = *reinterpret_cast<const uint4*>(hl + (size_t)s * CIN + g * 8);
        float2 p0 = upk(hv.x), p1 = upk(hv.y), p2 = upk(hv.z), p3 = upk(hv.w);
        float2 q0 = upk(lv.x), q1 = upk(lv.y), q2 = upk(lv.z), q3 = upk(lv.w);
        a[0] += p0.x + q0.x; a[1] += p0.y + q0.y;
        a[2] += p1.x + q1.x; a[3] += p1.y + q1.y;
        a[4] += p2.x + q2.x; a[5] += p2.y + q2.y;
        a[6] += p3.x + q3.x; a[7] += p3.y + q3.y;
    }
    uint4 hw, lw;
    float l0, l1;
    hw.x = pack_hi(a[0], a[1], l0, l1); lw.x = pack_bf2(l0, l1);
    hw.y = pack_hi(a[2], a[3], l0, l1); lw.y = pack_bf2(l0, l1);
    hw.z = pack_hi(a[4], a[5], l0, l1); lw.z = pack_bf2(l0, l1);
    hw.w = pack_hi(a[6], a[7], l0, l1); lw.w = pack_bf2(l0, l1);
    *reinterpret_cast<uint4*>(mh + (size_t)node * CIN + g * 8) = hw;
    *reinterpret_cast<uint4*>(ml + (size_t)node * CIN + g * 8) = lw;
}

// ---------------- x split ----------------
__global__ void k_split_x(const float* __restrict__ x,
                          __nv_bfloat16* __restrict__ xh, __nv_bfloat16* __restrict__ xl) {
    int t = blockIdx.x * 256 + threadIdx.x;
    if (t >= N_NODES * 8) return;
    const float4* p = reinterpret_cast<const float4*>(x + (size_t)t * 8);
    float4 v0 = p[0], v1 = p[1];
    uint4 hw, lw;
    float l0, l1;
    hw.x = pack_hi(v0.x, v0.y, l0, l1); lw.x = pack_bf2(l0, l1);
    hw.y = pack_hi(v0.z, v0.w, l0, l1); lw.y = pack_bf2(l0, l1);
    hw.z = pack_hi(v1.x, v1.y, l0, l1); lw.z = pack_bf2(l0, l1);
    hw.w = pack_hi(v1.z, v1.w, l0, l1); lw.w = pack_bf2(l0, l1);
    *reinterpret_cast<uint4*>(xh + (size_t)t * 8) = hw;
    *reinterpret_cast<uint4*>(xl + (size_t)t * 8) = lw;
}

// ---------------- weight prep ----------------
template <int CIN, int COUT>
__global__ void k_prep_w(const float* __restrict__ Wl, const float* __restrict__ Wr,
                         __nv_bfloat16* __restrict__ Whi, __nv_bfloat16* __restrict__ Wlo) {
    const int K = 2 * CIN;
    int t = blockIdx.x * 256 + threadIdx.x;
    if (t >= 6 * K * COUT) return;
    int n = t % COUT;
    int k = (t / COUT) % K;
    int d = t / (COUT * K);
    float v = (k < CIN) ? Wl[((size_t)d * CIN + k) * COUT + n]
                        : Wr[((size_t)d * CIN + (k - CIN)) * COUT + n];
    __nv_bfloat16 hi = __float2bfloat16_rn(v);
    float lo = v - __bfloat162float(hi);
    size_t o = ((size_t)(d * COUT + n)) * K + k;
    Whi[o] = hi;
    Wlo[o] = __float2bfloat16_rn(lo);
}

// ---------------- pipelined mma.sync bucketed GEMM + fused logit epilogue ----------------
// Tile 128(M) x 128(N), K chunk 64, cp.async double-buffered; warps 4(M) x 2(N).
template <int CIN, int COUT>
__global__ __launch_bounds__(256, 1)
void mf_gemm(const __nv_bfloat16* __restrict__ hp_hi, const __nv_bfloat16* __restrict__ hp_lo,
             const __nv_bfloat16* __restrict__ Whi, const __nv_bfloat16* __restrict__ Wlo,
             const float* __restrict__ bl,
             const float* __restrict__ Wf, int loff,
             __nv_bfloat16* __restrict__ nx_hi, __nv_bfloat16* __restrict__ nx_lo,
             float* __restrict__ logit) {
    constexpr int K     = 2 * CIN;
    constexpr int NCH   = K / 64;
    constexpr int NSLAB = COUT / 128;
    constexpr uint32_t STG = 65536;

    extern __shared__ char smem[];
    __shared__ int rows_s[128];

    const int slab = blockIdx.x % NSLAB;
    const int tile = blockIdx.x / NSLAB;
    const int d    = blockIdx.y;
    const int M    = g_meta[d];
    const int m0   = tile * 128;
    if (m0 >= M) return;
    const int base = g_meta[8 + d];
    const int n0g  = slab * 128;
    const int tid  = threadIdx.x;
    const int lane = tid & 31, wid = tid >> 5;
    const int wm   = wid & 3, wn = wid >> 2;

    if (tid < 128) {
        int mi = m0 + tid;
        rows_s[tid] = (mi < M) ? g_perm[base + mi] : -1;
    }
    __syncthreads();

    const uint32_t sb = smem_u32(smem);

    auto load_chunk = [&](int c, int buf) {
        const __nv_bfloat16 *ah, *al;
        int kl;
        if (c * 64 < CIN) { ah = g_msg_hi; al = g_msg_lo; kl = c * 64; }
        else              { ah = hp_hi;    al = hp_lo;    kl = c * 64 - CIN; }
        uint32_t s0 = sb + buf * STG;
#pragma unroll
        for (int it = 0; it < 4; it++) {
            int idx = it * 256 + tid;
            int row = idx >> 3, seg = idx & 7;
            int node = rows_s[row];
            uint32_t doff = (uint32_t)(row * 128) + (uint32_t)((seg * 16) ^ ((row & 7) << 4));
            size_t go = (size_t)(node < 0 ? 0 : node) * CIN + kl + seg * 8;
            uint32_t sz = (node < 0) ? 0u : 16u;
            cp_async16(s0 + doff, ah + go, sz);
            cp_async16(s0 + 16384 + doff, al + go, sz);
        }
#pragma unroll
        for (int it = 0; it < 4; it++) {
            int idx = it * 256 + tid;
            int n = idx >> 3, seg = idx & 7;
            uint32_t doff = (uint32_t)(n * 128) + (uint32_t)((seg * 16) ^ ((n & 7) << 4));
            size_t go = ((size_t)(d * COUT + n0g + n)) * K + c * 64 + seg * 8;
            cp_async16(s0 + 32768 + doff, Whi + go, 16);
            cp_async16(s0 + 49152 + doff, Wlo + go, 16);
        }
        asm volatile("cp.async.commit_group;" ::: "memory");
    };

    float acc[2][8][4];
#pragma unroll
    for (int t = 0; t < 2; t++)
#pragma unroll
        for (int u = 0; u < 8; u++)
#pragma unroll
            for (int i = 0; i < 4; i++) acc[t][u][i] = 0.f;

    load_chunk(0, 0);

    for (int c = 0; c < NCH; c++) {
        if (c + 1 < NCH) {
            load_chunk(c + 1, (c + 1) & 1);
            asm volatile("cp.async.wait_group 1;" ::: "memory");
        } else {
            asm volatile("cp.async.wait_group 0;" ::: "memory");
        }
        __syncthreads();

        uint32_t s0 = sb + (uint32_t)(c & 1) * STG;
        uint32_t sAh = s0, sAl = s0 + 16384, sBh = s0 + 32768, sBl = s0 + 49152;
#pragma unroll
        for (int kk = 0; kk < 4; kk++) {
            uint32_t a_hi[2][4], a_lo[2][4];
            const int mrow = wm * 32 + (lane & 15);
            const int kseg = lane >> 4;
#pragma unroll
            for (int t = 0; t < 2; t++) {
                int row = mrow + t * 16;
                uint32_t off = (uint32_t)(row * 128) +
                               (uint32_t)((kk * 32 + kseg * 16) ^ ((row & 7) << 4));
                ldsm_x4(a_hi[t], sAh + off);
                ldsm_x4(a_lo[t], sAl + off);
            }
            const int nlane = wn * 64 + (lane & 7);
            const int bseg  = (lane >> 3) & 1;
            uint32_t b_hi[8][2], b_lo[8][2];
#pragma unroll
            for (int u = 0; u < 8; u++) {
                int n = nlane + u * 8;
                uint32_t off = (uint32_t)(n * 128) +
                               (uint32_t)((kk * 32 + bseg * 16) ^ ((n & 7) << 4));
                ldsm_x2(b_hi[u], sBh + off);
                ldsm_x2(b_lo[u], sBl + off);
            }
#pragma unroll
            for (int t = 0; t < 2; t++)
#pragma unroll
                for (int u = 0; u < 8; u++) {
                    mma_16816(acc[t][u], a_hi[t], b_hi[u]);
                    mma_16816(acc[t][u], a_hi[t], b_lo[u]);
                    mma_16816(acc[t][u], a_lo[t], b_hi[u]);
                }
        }
        __syncthreads();
    }

    // ---- epilogue: bias + split bf16 out + fused logit dot ----
    float lgA[2][2], lgB[2][2];
#pragma unroll
    for (int t = 0; t < 2; t++) { lgA[t][0] = lgA[t][1] = lgB[t][0] = lgB[t][1] = 0.f; }

#pragma unroll
    for (int t = 0; t < 2; t++) {
        int r0 = wm * 32 + t * 16 + (lane >> 2);
        int nd0 = rows_s[r0], nd1 = rows_s[r0 + 8];
#pragma unroll
        for (int u = 0; u < 8; u++) {
            int col = n0g + wn * 64 + u * 8 + (lane & 3) * 2;
            float2 bv = *reinterpret_cast<const float2*>(bl + d * COUT + col);
            float4 wf = *reinterpret_cast<const float4*>(Wf + 2 * (loff + col));
            if (nd0 >= 0) {
                float ox = acc[t][u][0] + bv.x, oy = acc[t][u][1] + bv.y;
                float lx, ly;
                uint32_t hw = pack_hi(ox, oy, lx, ly);
                *reinterpret_cast<uint32_t*>(nx_hi + (size_t)nd0 * COUT + col) = hw;
                *reinterpret_cast<uint32_t*>(nx_lo + (size_t)nd0 * COUT + col) = pack_bf2(lx, ly);
                lgA[t][0] += ox * wf.x + oy * wf.z;
                lgB[t][0] += ox * wf.y + oy * wf.w;
            }
            if (nd1 >= 0) {
                float ox = acc[t][u][2] + bv.x, oy = acc[t][u][3] + bv.y;
                float lx, ly;
                uint32_t hw = pack_hi(ox, oy, lx, ly);
                *reinterpret_cast<uint32_t*>(nx_hi + (size_t)nd1 * COUT + col) = hw;
                *reinterpret_cast<uint32_t*>(nx_lo + (size_t)nd1 * COUT + col) = pack_bf2(lx, ly);
                lgA[t][1] += ox * wf.x + oy * wf.z;
                lgB[t][1] += ox * wf.y + oy * wf.w;
            }
        }
    }
#pragma unroll
    for (int t = 0; t < 2; t++)
#pragma unroll
        for (int r = 0; r < 2; r++) {
            float v0 = lgA[t][r], v1 = lgB[t][r];
            v0 += __shfl_xor_sync(0xFFFFFFFFu, v0, 1);
            v0 += __shfl_xor_sync(0xFFFFFFFFu, v0, 2);
            v1 += __shfl_xor_sync(0xFFFFFFFFu, v1, 1);
            v1 += __shfl_xor_sync(0xFFFFFFFFu, v1, 2);
            int rr = wm * 32 + t * 16 + (lane >> 2) + r * 8;
            int nd = rows_s[rr];
            if ((lane & 3) == 0 && nd >= 0) {
                atomicAdd(&logit[nd * 2 + 0], v0);
                atomicAdd(&logit[nd * 2 + 1], v1);
            }
        }
}

// ---------------- pool + finalize ----------------
__global__ void k_zero_pool() {
    int i = blockIdx.x * 256 + threadIdx.x;
    if (i < N_GRAPHS * 256 / 4)
        reinterpret_cast<float4*>(g_pool)[i] = make_float4(0.f, 0.f, 0.f, 0.f);
}
__global__ void k_pool(const int* __restrict__ batch,
                       const __nv_bfloat16* __restrict__ hh, const __nv_bfloat16* __restrict__ hl) {
    int t = blockIdx.x * 256 + threadIdx.x;   // N_NODES * 64 threads, 4 elems each
    int i = t >> 6;
    int f = (t & 63) * 4;
    if (i >= N_NODES) return;
    uint2 hv = *reinterpret_cast<const uint2*>(hh + (size_t)i * 256 + f);
    uint2 lv = *reinterpret_cast<const uint2*>(hl + (size_t)i * 256 + f);
    float2 p0 = upk(hv.x), p1 = upk(hv.y), q0 = upk(lv.x), q1 = upk(lv.y);
    float4 v = make_float4(p0.x + q0.x, p0.y + q0.y, p1.x + q1.x, p1.y + q1.y);
    red_add_v4(g_pool + (size_t)batch[i] * 256 + f, v);
}
__global__ void k_pool_dot(const float* __restrict__ Wf) {
    int gt = blockIdx.x * 256 + threadIdx.x;
    int g = gt >> 5, lane = gt & 31;
    if (g >= N_GRAPHS) return;
    float a0 = 0.f, a1 = 0.f;
#pragma unroll
    for (int k = lane; k < 256; k += 32) {
        float v = g_pool[(size_t)g * 256 + k];
        float2 w = *reinterpret_cast<const float2*>(Wf + 2 * (768 + k));
        a0 += v * w.x; a1 += v * w.y;
    }
#pragma unroll
    for (int o = 16; o > 0; o >>= 1) {
        a0 += __shfl_xor_sync(0xFFFFFFFFu, a0, o);
        a1 += __shfl_xor_sync(0xFFFFFFFFu, a1, o);
    }
    if (lane == 0) *reinterpret_cast<float2*>(g_glogit + g * 2) = make_float2(a0, a1);
}
__global__ void k_finalize(const int* __restrict__ batch, const float* __restrict__ bf,
                           float* __restrict__ out) {
    int i = blockIdx.x * 256 + threadIdx.x;
    if (i >= N_NODES) return;
    float2 nl = *reinterpret_cast<const float2*>(g_logit + i * 2);
    float2 gl = *reinterpret_cast<const float2*>(g_glogit + batch[i] * 2);
    float a0 = nl.x + gl.x + bf[0];
    float a1 = nl.y + gl.y + bf[1];
    float m  = fmaxf(a0, a1);
    float e0 = expf(a0 - m), e1 = expf(a1 - m);
    float s  = e0 + e1;
    *reinterpret_cast<float2*>(out + (size_t)i * 2) = make_float2(e0 / s, e1 / s);
}

// ---------------- launch ----------------
extern "C" void kernel_launch(void* const* d_in, const int* in_sizes, int n_in,
                              void* d_out, int out_size) {
    (void)in_sizes; (void)n_in; (void)out_size;
    const float* x     = (const float*)d_in[0];
    const int*   ei    = (const int*)d_in[1];
    const int*   batch = (const int*)d_in[2];
    const float* Wl0 = (const float*)d_in[3];
    const float* bl0 = (const float*)d_in[4];
    const float* Wr0 = (const float*)d_in[5];
    const float* Wl1 = (const float*)d_in[6];
    const float* bl1 = (const float*)d_in[7];
    const float* Wr1 = (const float*)d_in[8];
    const float* Wl2 = (const float*)d_in[9];
    const float* bl2 = (const float*)d_in[10];
    const float* Wr2 = (const float*)d_in[11];
    const float* Wl3 = (const float*)d_in[12];
    const float* bl3 = (const float*)d_in[13];
    const float* Wr3 = (const float*)d_in[14];
    const float* Wf  = (const float*)d_in[15];
    const float* bf  = (const float*)d_in[16];
    float* out = (float*)d_out;

    const int* src = ei;
    const int* dst = ei + N_EDGES;

    __nv_bfloat16 *whi, *wlo, *sah, *sal, *sbh, *sbl, *mh, *ml;
    float* lg;
    cudaGetSymbolAddress((void**)&whi, g_whi);
    cudaGetSymbolAddress((void**)&wlo, g_wlo);
    cudaGetSymbolAddress((void**)&sah, g_sa_hi);
    cudaGetSymbolAddress((void**)&sal, g_sa_lo);
    cudaGetSymbolAddress((void**)&sbh, g_sb_hi);
    cudaGetSymbolAddress((void**)&sbl, g_sb_lo);
    cudaGetSymbolAddress((void**)&mh, g_msg_hi);
    cudaGetSymbolAddress((void**)&ml, g_msg_lo);
    cudaGetSymbolAddress((void**)&lg, g_logit);

    const int SMEM = 131072;
    cudaFuncSetAttribute(mf_gemm<64, 128>,  cudaFuncAttributeMaxDynamicSharedMemorySize, SMEM);
    cudaFuncSetAttribute(mf_gemm<128, 128>, cudaFuncAttributeMaxDynamicSharedMemorySize, SMEM);
    cudaFuncSetAttribute(mf_gemm<128, 256>, cudaFuncAttributeMaxDynamicSharedMemorySize, SMEM);
    cudaFuncSetAttribute(mf_gemm<256, 256>, cudaFuncAttributeMaxDynamicSharedMemorySize, SMEM);

    const int NB_N = (N_NODES + 255) / 256;
    const int NB_E = (N_EDGES + 255) / 256;
    const int T128 = (N_NODES + 127) / 128;  // 1563

    // degree + CSR + buckets (also zeros per-node logits)
    k_zero_deg<<<NB_N, 256>>>();
    k_deg<<<NB_E, 256>>>(dst);
    k_scan1<<<NBLK_SCAN, 256>>>();
    k_scan2<<<1, 1024>>>();
    k_scan3<<<NB_N, 256>>>();
    k_csr_fill<<<NB_E, 256>>>(src, dst);
    k_bcount<<<NB_N, 256>>>();
    k_offsets<<<1, 1>>>();
    k_fill<<<NB_N, 256>>>();

    // weight prep + x split
    k_prep_w<64, 128><<<(6 * 128 * 128 + 255) / 256, 256>>>(Wl0, Wr0, whi + WOFF0, wlo + WOFF0);
    k_prep_w<128, 128><<<(6 * 256 * 128 + 255) / 256, 256>>>(Wl1, Wr1, whi + WOFF1, wlo + WOFF1);
    k_prep_w<128, 256><<<(6 * 256 * 256 + 255) / 256, 256>>>(Wl2, Wr2, whi + WOFF2, wlo + WOFF2);
    k_prep_w<256, 256><<<(6 * 512 * 256 + 255) / 256, 256>>>(Wl3, Wr3, whi + WOFF3, wlo + WOFF3);
    k_split_x<<<(N_NODES * 8 + 255) / 256, 256>>>(x, sah, sal);

    // layer 0: 64 -> 128   (in sa, out sb)
    k_agg<64><<<(N_NODES * 8 + 255) / 256, 256>>>(sah, sal, mh, ml);
    mf_gemm<64, 128><<<dim3(T128, 6), 256, SMEM>>>(sah, sal, whi + WOFF0, wlo + WOFF0, bl0, Wf, 0, sbh, sbl, lg);

    // layer 1: 128 -> 128  (in sb, out sa)
    k_agg<128><<<(N_NODES * 16 + 255) / 256, 256>>>(sbh, sbl, mh, ml);
    mf_gemm<128, 128><<<dim3(T128, 6), 256, SMEM>>>(sbh, sbl, whi + WOFF1, wlo + WOFF1, bl1, Wf, 128, sah, sal, lg);

    // layer 2: 128 -> 256  (in sa, out sb)
    k_agg<128><<<(N_NODES * 16 + 255) / 256, 256>>>(sah, sal, mh, ml);
    mf_gemm<128, 256><<<dim3(T128 * 2, 6), 256, SMEM>>>(sah, sal, whi + WOFF2, wlo + WOFF2, bl2, Wf, 256, sbh, sbl, lg);

    // layer 3: 256 -> 256  (in sb, out sa)
    k_agg<256><<<(N_NODES * 32 + 255) / 256, 256>>>(sbh, sbl, mh, ml);
    mf_gemm<256, 256><<<dim3(T128 * 2, 6), 256, SMEM>>>(sbh, sbl, whi + WOFF3, wlo + WOFF3, bl3, Wf, 512, sah, sal, lg);

    // pool + finalize
    k_zero_pool<<<(N_GRAPHS * 64 + 255) / 256, 256>>>();
    k_pool<<<(N_NODES * 64 + 255) / 256, 256>>>(batch, sah, sal);
    k_pool_dot<<<(N_GRAPHS * 32 + 255) / 256, 256>>>(Wf);
    k_finalize<<<NB_N, 256>>>(batch, bf, out);
}

// round 8
// speedup vs baseline: 2.3675x; 1.0366x over previous
#include <cuda_runtime.h>
#include <cuda_bf16.h>
#include <cstdint>

#define N_NODES  200000
#define N_EDGES  800000
#define N_GRAPHS 4096
#define MAXDEG   5
#define NBLK_SCAN 782   // ceil(N_NODES/256)

// ---------------- scratch (static __device__, no allocs) ----------------
__device__ float g_pool[N_GRAPHS * 256];
__device__ float g_logit[N_NODES * 2];
__device__ float g_glogit[N_GRAPHS * 2];
__device__ __nv_bfloat16 g_msg_hi[N_NODES * 256];
__device__ __nv_bfloat16 g_msg_lo[N_NODES * 256];
__device__ __nv_bfloat16 g_sa_hi[N_NODES * 256];
__device__ __nv_bfloat16 g_sa_lo[N_NODES * 256];
__device__ __nv_bfloat16 g_sb_hi[N_NODES * 256];
__device__ __nv_bfloat16 g_sb_lo[N_NODES * 256];
__device__ int   g_deg[N_NODES];
__device__ int   g_cur[N_NODES];
__device__ int   g_perm[N_NODES];
__device__ int   g_csr_off[N_NODES + 1];
__device__ int   g_csr[N_EDGES];
__device__ int   g_bsum[1024];
__device__ int   g_bpre[1024];
__device__ int   g_meta[64];

// split-bf16 transposed weights: [d][n][k] K-major (k spans 2*CIN: Wl then Wr)
#define WOFF0 0
#define WOFF1 98304
#define WOFF2 294912
#define WOFF3 688128
#define WTOT  1474560
__device__ __nv_bfloat16 g_whi[WTOT];
__device__ __nv_bfloat16 g_wlo[WTOT];

// ---------------- helpers (portable PTX only) ----------------
__device__ __forceinline__ uint32_t smem_u32(const void* p) {
    uint32_t a;
    asm("{ .reg .u64 t; cvta.to.shared.u64 t, %1; cvt.u32.u64 %0, t; }" : "=r"(a) : "l"(p));
    return a;
}
__device__ __forceinline__ void red_add_v2(float* addr, float x, float y) {
    asm volatile("red.global.add.v2.f32 [%0], {%1,%2};"
                 :: "l"(addr), "f"(x), "f"(y) : "memory");
}
__device__ __forceinline__ void ldsm_x4(uint32_t* r, uint32_t addr) {
    asm volatile("ldmatrix.sync.aligned.m8n8.x4.shared.b16 {%0,%1,%2,%3}, [%4];"
                 : "=r"(r[0]), "=r"(r[1]), "=r"(r[2]), "=r"(r[3]) : "r"(addr));
}
__device__ __forceinline__ void ldsm_x2(uint32_t* r, uint32_t addr) {
    asm volatile("ldmatrix.sync.aligned.m8n8.x2.shared.b16 {%0,%1}, [%2];"
                 : "=r"(r[0]), "=r"(r[1]) : "r"(addr));
}
__device__ __forceinline__ void mma_16816(float* c, const uint32_t* a, const uint32_t* b) {
    asm volatile("mma.sync.aligned.m16n8k16.row.col.f32.bf16.bf16.f32 "
                 "{%0,%1,%2,%3}, {%4,%5,%6,%7}, {%8,%9}, {%0,%1,%2,%3};"
                 : "+f"(c[0]), "+f"(c[1]), "+f"(c[2]), "+f"(c[3])
                 : "r"(a[0]), "r"(a[1]), "r"(a[2]), "r"(a[3]), "r"(b[0]), "r"(b[1]));
}
__device__ __forceinline__ void cp_async16(uint32_t s, const void* g, uint32_t sz) {
    asm volatile("cp.async.cg.shared.global [%0], [%1], 16, %2;"
                 :: "r"(s), "l"(g), "r"(sz) : "memory");
}
__device__ __forceinline__ uint32_t pack_hi(float x, float y, float& lx, float& ly) {
    __nv_bfloat16 h0 = __float2bfloat16_rn(x), h1 = __float2bfloat16_rn(y);
    lx = x - __bfloat162float(h0);
    ly = y - __bfloat162float(h1);
    __nv_bfloat162 hp(h0, h1);
    return *reinterpret_cast<uint32_t*>(&hp);
}
__device__ __forceinline__ uint32_t pack_bf2(float x, float y) {
    __nv_bfloat162 p = __floats2bfloat162_rn(x, y);
    return *reinterpret_cast<uint32_t*>(&p);
}
__device__ __forceinline__ float2 upk(uint32_t u) {
    return __bfloat1622float2(*reinterpret_cast<__nv_bfloat162*>(&u));
}

// ---------------- degree / scan / csr / buckets ----------------
__global__ void k_zero_deg() {
    int i = blockIdx.x * 256 + threadIdx.x;
    if (i < N_NODES) {
        g_deg[i] = 0; g_cur[i] = 0;
        *reinterpret_cast<float2*>(g_logit + i * 2) = make_float2(0.f, 0.f);
    }
    if (i < 64) g_meta[i] = 0;
}
__global__ void k_deg(const int* __restrict__ dst) {
    int e = blockIdx.x * 256 + threadIdx.x;
    if (e < N_EDGES) atomicAdd(&g_deg[dst[e]], 1);
}
__global__ void k_scan1() {
    __shared__ int s[256];
    int b = blockIdx.x, t = threadIdx.x, i = b * 256 + t;
    int v = (i < N_NODES) ? g_deg[i] : 0;
    s[t] = v;
    __syncthreads();
#pragma unroll
    for (int o = 1; o < 256; o <<= 1) {
        int u = (t >= o) ? s[t - o] : 0;
        __syncthreads();
        s[t] += u;
        __syncthreads();
    }
    if (i < N_NODES) g_csr_off[i] = s[t] - v;
    if (t == 255) g_bsum[b] = s[255];
}
__global__ void k_scan2() {
    __shared__ int s[1024];
    int t = threadIdx.x;
    int v = (t < NBLK_SCAN) ? g_bsum[t] : 0;
    s[t] = v;
    __syncthreads();
#pragma unroll
    for (int o = 1; o < 1024; o <<= 1) {
        int u = (t >= o) ? s[t - o] : 0;
        __syncthreads();
        s[t] += u;
        __syncthreads();
    }
    if (t < NBLK_SCAN) g_bpre[t] = s[t] - v;
}
__global__ void k_scan3() {
    int i = blockIdx.x * 256 + threadIdx.x;
    if (i < N_NODES) g_csr_off[i] += g_bpre[i >> 8];
    if (i == 0) g_csr_off[N_NODES] = N_EDGES;
}
__global__ void k_csr_fill(const int* __restrict__ src, const int* __restrict__ dst) {
    int e = blockIdx.x * 256 + threadIdx.x;
    if (e < N_EDGES) {
        int d = dst[e];
        int p = atomicAdd(&g_cur[d], 1);
        g_csr[g_csr_off[d] + p] = src[e];
    }
}
__global__ void k_bcount() {
    int i = blockIdx.x * 256 + threadIdx.x;
    if (i < N_NODES) atomicAdd(&g_meta[min(g_deg[i], MAXDEG)], 1);
}
__global__ void k_offsets() {
    int s = 0;
    for (int d = 0; d <= MAXDEG; d++) { g_meta[8 + d] = s; s += g_meta[d]; }
}
__global__ void k_fill() {
    int i = blockIdx.x * 256 + threadIdx.x;
    if (i < N_NODES) {
        int d = min(g_deg[i], MAXDEG);
        int p = atomicAdd(&g_meta[16 + d], 1);
        g_perm[g_meta[8 + d] + p] = i;
    }
}

// ---------------- CSR aggregation (split input -> split msg), 2-way MLP ----------------
template <int CIN>
__global__ void k_agg(const __nv_bfloat16* __restrict__ hh, const __nv_bfloat16* __restrict__ hl,
                      __nv_bfloat16* __restrict__ mh, __nv_bfloat16* __restrict__ ml) {
    const int PER = CIN / 8;
    int t = blockIdx.x * 256 + threadIdx.x;
    int node = t / PER, g = t % PER;
    if (node >= N_NODES) return;
    int j0 = g_csr_off[node], j1 = g_csr_off[node + 1];
    float a[8];
#pragma unroll
    for (int i = 0; i < 8; i++) a[i] = 0.f;
    int j = j0;
    for (; j + 2 <= j1; j += 2) {
        int s0 = g_csr[j], s1 = g_csr[j + 1];
        uint4 h0 = *reinterpret_cast<const uint4*>(hh + (size_t)s0 * CIN + g * 8);
        uint4 l0 = *reinterpret_cast<const uint4*>(hl + (size_t)s0 * CIN + g * 8);
        uint4 h1 = *reinterpret_cast<const uint4*>(hh + (size_t)s1 * CIN + g * 8);
        uint4 l1 = *reinterpret_cast<const uint4*>(hl + (size_t)s1 * CIN + g * 8);
        float2 p0 = upk(h0.x), p1 = upk(h0.y), p2 = upk(h0.z), p3 = upk(h0.w);
        float2 q0 = upk(l0.x), q1 = upk(l0.y), q2 = upk(l0.z), q3 = upk(l0.w);
        float2 r0 = upk(h1.x), r1 = upk(h1.y), r2 = upk(h1.z), r3 = upk(h1.w);
        float2 s0v = upk(l1.x), s1v = upk(l1.y), s2v = upk(l1.z), s3v = upk(l1.w);
        a[0] += (p0.x + q0.x) + (r0.x + s0v.x); a[1] += (p0.y + q0.y) + (r0.y + s0v.y);
        a[2] += (p1.x + q1.x) + (r1.x + s1v.x); a[3] += (p1.y + q1.y) + (r1.y + s1v.y);
        a[4] += (p2.x + q2.x) + (r2.x + s2v.x); a[5] += (p2.y + q2.y) + (r2.y + s2v.y);
        a[6] += (p3.x + q3.x) + (r3.x + s3v.x); a[7] += (p3.y + q3.y) + (r3.y + s3v.y);
    }
    if (j < j1) {
        int s0 = g_csr[j];
        uint4 hv = *reinterpret_cast<const uint4*>(hh + (size_t)s0 * CIN + g * 8);
        uint4 lv = *reinterpret_cast<const uint4*>(hl + (size_t)s0 * CIN + g * 8);
        float2 p0 = upk(hv.x), p1 = upk(hv.y), p2 = upk(hv.z), p3 = upk(hv.w);
        float2 q0 = upk(lv.x), q1 = upk(lv.y), q2 = upk(lv.z), q3 = upk(lv.w);
        a[0] += p0.x + q0.x; a[1] += p0.y + q0.y;
        a[2] += p1.x + q1.x; a[3] += p1.y + q1.y;
        a[4] += p2.x + q2.x; a[5] += p2.y + q2.y;
        a[6] += p3.x + q3.x; a[7] += p3.y + q3.y;
    }
    uint4 hw, lw;
    float l0, l1;
    hw.x = pack_hi(a[0], a[1], l0, l1); lw.x = pack_bf2(l0, l1);
    hw.y = pack_hi(a[2], a[3], l0, l1); lw.y = pack_bf2(l0, l1);
    hw.z = pack_hi(a[4], a[5], l0, l1); lw.z = pack_bf2(l0, l1);
    hw.w = pack_hi(a[6], a[7], l0, l1); lw.w = pack_bf2(l0, l1);
    *reinterpret_cast<uint4*>(mh + (size_t)node * CIN + g * 8) = hw;
    *reinterpret_cast<uint4*>(ml + (size_t)node * CIN + g * 8) = lw;
}

// ---------------- x split ----------------
__global__ void k_split_x(const float* __restrict__ x,
                          __nv_bfloat16* __restrict__ xh, __nv_bfloat16* __restrict__ xl) {
    int t = blockIdx.x * 256 + threadIdx.x;
    if (t >= N_NODES * 8) return;
    const float4* p = reinterpret_cast<const float4*>(x + (size_t)t * 8);
    float4 v0 = p[0], v1 = p[1];
    uint4 hw, lw;
    float l0, l1;
    hw.x = pack_hi(v0.x, v0.y, l0, l1); lw.x = pack_bf2(l0, l1);
    hw.y = pack_hi(v0.z, v0.w, l0, l1); lw.y = pack_bf2(l0, l1);
    hw.z = pack_hi(v1.x, v1.y, l0, l1); lw.z = pack_bf2(l0, l1);
    hw.w = pack_hi(v1.z, v1.w, l0, l1); lw.w = pack_bf2(l0, l1);
    *reinterpret_cast<uint4*>(xh + (size_t)t * 8) = hw;
    *reinterpret_cast<uint4*>(xl + (size_t)t * 8) = lw;
}

// ---------------- weight prep ----------------
template <int CIN, int COUT>
__global__ void k_prep_w(const float* __restrict__ Wl, const float* __restrict__ Wr,
                         __nv_bfloat16* __restrict__ Whi, __nv_bfloat16* __restrict__ Wlo) {
    const int K = 2 * CIN;
    int t = blockIdx.x * 256 + threadIdx.x;
    if (t >= 6 * K * COUT) return;
    int n = t % COUT;
    int k = (t / COUT) % K;
    int d = t / (COUT * K);
    float v = (k < CIN) ? Wl[((size_t)d * CIN + k) * COUT + n]
                        : Wr[((size_t)d * CIN + (k - CIN)) * COUT + n];
    __nv_bfloat16 hi = __float2bfloat16_rn(v);
    float lo = v - __bfloat162float(hi);
    size_t o = ((size_t)(d * COUT + n)) * K + k;
    Whi[o] = hi;
    Wlo[o] = __float2bfloat16_rn(lo);
}

// ---------------- pipelined mma.sync bucketed GEMM + fused logit (+pool) epilogue ----------------
// Tile 128(M) x 128(N), K chunk 64, cp.async double-buffered; warps 4(M) x 2(N).
// POOL=false: epilogue writes split bf16 hidden state. POOL=true (last layer):
// epilogue red-adds directly into g_pool[batch[node]*256+col]; no hidden-state store.
template <int CIN, int COUT, bool POOL>
__global__ __launch_bounds__(256, 1)
void mf_gemm(const __nv_bfloat16* __restrict__ hp_hi, const __nv_bfloat16* __restrict__ hp_lo,
             const __nv_bfloat16* __restrict__ Whi, const __nv_bfloat16* __restrict__ Wlo,
             const float* __restrict__ bl,
             const float* __restrict__ Wf, int loff,
             __nv_bfloat16* __restrict__ nx_hi, __nv_bfloat16* __restrict__ nx_lo,
             float* __restrict__ logit,
             const int* __restrict__ batch, float* __restrict__ pool) {
    constexpr int K     = 2 * CIN;
    constexpr int NCH   = K / 64;
    constexpr int NSLAB = COUT / 128;
    constexpr uint32_t STG = 65536;

    extern __shared__ char smem[];
    __shared__ int rows_s[128];
    __shared__ int bat_s[128];

    const int slab = blockIdx.x % NSLAB;
    const int tile = blockIdx.x / NSLAB;
    const int d    = blockIdx.y;
    const int M    = g_meta[d];
    const int m0   = tile * 128;
    if (m0 >= M) return;
    const int base = g_meta[8 + d];
    const int n0g  = slab * 128;
    const int tid  = threadIdx.x;
    const int lane = tid & 31, wid = tid >> 5;
    const int wm   = wid & 3, wn = wid >> 2;

    if (tid < 128) {
        int mi = m0 + tid;
        int nd = (mi < M) ? g_perm[base + mi] : -1;
        rows_s[tid] = nd;
        if (POOL) bat_s[tid] = (nd >= 0) ? batch[nd] : 0;
    }
    __syncthreads();

    const uint32_t sb = smem_u32(smem);

    auto load_chunk = [&](int c, int buf) {
        const __nv_bfloat16 *ah, *al;
        int kl;
        if (c * 64 < CIN) { ah = g_msg_hi; al = g_msg_lo; kl = c * 64; }
        else              { ah = hp_hi;    al = hp_lo;    kl = c * 64 - CIN; }
        uint32_t s0 = sb + buf * STG;
#pragma unroll
        for (int it = 0; it < 4; it++) {
            int idx = it * 256 + tid;
            int row = idx >> 3, seg = idx & 7;
            int node = rows_s[row];
            uint32_t doff = (uint32_t)(row * 128) + (uint32_t)((seg * 16) ^ ((row & 7) << 4));
            size_t go = (size_t)(node < 0 ? 0 : node) * CIN + kl + seg * 8;
            uint32_t sz = (node < 0) ? 0u : 16u;
            cp_async16(s0 + doff, ah + go, sz);
            cp_async16(s0 + 16384 + doff, al + go, sz);
        }
#pragma unroll
        for (int it = 0; it < 4; it++) {
            int idx = it * 256 + tid;
            int n = idx >> 3, seg = idx & 7;
            uint32_t doff = (uint32_t)(n * 128) + (uint32_t)((seg * 16) ^ ((n & 7) << 4));
            size_t go = ((size_t)(d * COUT + n0g + n)) * K + c * 64 + seg * 8;
            cp_async16(s0 + 32768 + doff, Whi + go, 16);
            cp_async16(s0 + 49152 + doff, Wlo + go, 16);
        }
        asm volatile("cp.async.commit_group;" ::: "memory");
    };

    float acc[2][8][4];
#pragma unroll
    for (int t = 0; t < 2; t++)
#pragma unroll
        for (int u = 0; u < 8; u++)
#pragma unroll
            for (int i = 0; i < 4; i++) acc[t][u][i] = 0.f;

    load_chunk(0, 0);

    for (int c = 0; c < NCH; c++) {
        if (c + 1 < NCH) {
            load_chunk(c + 1, (c + 1) & 1);
            asm volatile("cp.async.wait_group 1;" ::: "memory");
        } else {
            asm volatile("cp.async.wait_group 0;" ::: "memory");
        }
        __syncthreads();

        uint32_t s0 = sb + (uint32_t)(c & 1) * STG;
        uint32_t sAh = s0, sAl = s0 + 16384, sBh = s0 + 32768, sBl = s0 + 49152;
#pragma unroll
        for (int kk = 0; kk < 4; kk++) {
            uint32_t a_hi[2][4], a_lo[2][4];
            const int mrow = wm * 32 + (lane & 15);
            const int kseg = lane >> 4;
#pragma unroll
            for (int t = 0; t < 2; t++) {
                int row = mrow + t * 16;
                uint32_t off = (uint32_t)(row * 128) +
                               (uint32_t)((kk * 32 + kseg * 16) ^ ((row & 7) << 4));
                ldsm_x4(a_hi[t], sAh + off);
                ldsm_x4(a_lo[t], sAl + off);
            }
            const int nlane = wn * 64 + (lane & 7);
            const int bseg  = (lane >> 3) & 1;
            uint32_t b_hi[8][2], b_lo[8][2];
#pragma unroll
            for (int u = 0; u < 8; u++) {
                int n = nlane + u * 8;
                uint32_t off = (uint32_t)(n * 128) +
                               (uint32_t)((kk * 32 + bseg * 16) ^ ((n & 7) << 4));
                ldsm_x2(b_hi[u], sBh + off);
                ldsm_x2(b_lo[u], sBl + off);
            }
#pragma unroll
            for (int t = 0; t < 2; t++)
#pragma unroll
                for (int u = 0; u < 8; u++) {
                    mma_16816(acc[t][u], a_hi[t], b_hi[u]);
                    mma_16816(acc[t][u], a_hi[t], b_lo[u]);
                    mma_16816(acc[t][u], a_lo[t], b_hi[u]);
                }
        }
        __syncthreads();
    }

    // ---- epilogue: bias + (split bf16 out | pool red-add) + fused logit dot ----
    float lgA[2][2], lgB[2][2];
#pragma unroll
    for (int t = 0; t < 2; t++) { lgA[t][0] = lgA[t][1] = lgB[t][0] = lgB[t][1] = 0.f; }

#pragma unroll
    for (int t = 0; t < 2; t++) {
        int r0 = wm * 32 + t * 16 + (lane >> 2);
        int nd0 = rows_s[r0], nd1 = rows_s[r0 + 8];
        int b0 = POOL ? bat_s[r0] : 0, b1 = POOL ? bat_s[r0 + 8] : 0;
#pragma unroll
        for (int u = 0; u < 8; u++) {
            int col = n0g + wn * 64 + u * 8 + (lane & 3) * 2;
            float2 bv = *reinterpret_cast<const float2*>(bl + d * COUT + col);
            float4 wf = *reinterpret_cast<const float4*>(Wf + 2 * (loff + col));
            if (nd0 >= 0) {
                float ox = acc[t][u][0] + bv.x, oy = acc[t][u][1] + bv.y;
                if (POOL) {
                    red_add_v2(pool + (size_t)b0 * 256 + col, ox, oy);
                } else {
                    float lx, ly;
                    uint32_t hw = pack_hi(ox, oy, lx, ly);
                    *reinterpret_cast<uint32_t*>(nx_hi + (size_t)nd0 * COUT + col) = hw;
                    *reinterpret_cast<uint32_t*>(nx_lo + (size_t)nd0 * COUT + col) = pack_bf2(lx, ly);
                }
                lgA[t][0] += ox * wf.x + oy * wf.z;
                lgB[t][0] += ox * wf.y + oy * wf.w;
            }
            if (nd1 >= 0) {
                float ox = acc[t][u][2] + bv.x, oy = acc[t][u][3] + bv.y;
                if (POOL) {
                    red_add_v2(pool + (size_t)b1 * 256 + col, ox, oy);
                } else {
                    float lx, ly;
                    uint32_t hw = pack_hi(ox, oy, lx, ly);
                    *reinterpret_cast<uint32_t*>(nx_hi + (size_t)nd1 * COUT + col) = hw;
                    *reinterpret_cast<uint32_t*>(nx_lo + (size_t)nd1 * COUT + col) = pack_bf2(lx, ly);
                }
                lgA[t][1] += ox * wf.x + oy * wf.z;
                lgB[t][1] += ox * wf.y + oy * wf.w;
            }
        }
    }
#pragma unroll
    for (int t = 0; t < 2; t++)
#pragma unroll
        for (int r = 0; r < 2; r++) {
            float v0 = lgA[t][r], v1 = lgB[t][r];
            v0 += __shfl_xor_sync(0xFFFFFFFFu, v0, 1);
            v0 += __shfl_xor_sync(0xFFFFFFFFu, v0, 2);
            v1 += __shfl_xor_sync(0xFFFFFFFFu, v1, 1);
            v1 += __shfl_xor_sync(0xFFFFFFFFu, v1, 2);
            int rr = wm * 32 + t * 16 + (lane >> 2) + r * 8;
            int nd = rows_s[rr];
            if ((lane & 3) == 0 && nd >= 0) {
                atomicAdd(&logit[nd * 2 + 0], v0);
                atomicAdd(&logit[nd * 2 + 1], v1);
            }
        }
}

// ---------------- pool + finalize ----------------
__global__ void k_zero_pool() {
    int i = blockIdx.x * 256 + threadIdx.x;
    if (i < N_GRAPHS * 256 / 4)
        reinterpret_cast<float4*>(g_pool)[i] = make_float4(0.f, 0.f, 0.f, 0.f);
}
__global__ void k_pool_dot(const float* __restrict__ Wf) {
    int gt = blockIdx.x * 256 + threadIdx.x;
    int g = gt >> 5, lane = gt & 31;
    if (g >= N_GRAPHS) return;
    float a0 = 0.f, a1 = 0.f;
#pragma unroll
    for (int k = lane; k < 256; k += 32) {
        float v = g_pool[(size_t)g * 256 + k];
        float2 w = *reinterpret_cast<const float2*>(Wf + 2 * (768 + k));
        a0 += v * w.x; a1 += v * w.y;
    }
#pragma unroll
    for (int o = 16; o > 0; o >>= 1) {
        a0 += __shfl_xor_sync(0xFFFFFFFFu, a0, o);
        a1 += __shfl_xor_sync(0xFFFFFFFFu, a1, o);
    }
    if (lane == 0) *reinterpret_cast<float2*>(g_glogit + g * 2) = make_float2(a0, a1);
}
__global__ void k_finalize(const int* __restrict__ batch, const float* __restrict__ bf,
                           float* __restrict__ out) {
    int i = blockIdx.x * 256 + threadIdx.x;
    if (i >= N_NODES) return;
    float2 nl = *reinterpret_cast<const float2*>(g_logit + i * 2);
    float2 gl = *reinterpret_cast<const float2*>(g_glogit + batch[i] * 2);
    float a0 = nl.x + gl.x + bf[0];
    float a1 = nl.y + gl.y + bf[1];
    float m  = fmaxf(a0, a1);
    float e0 = expf(a0 - m), e1 = expf(a1 - m);
    float s  = e0 + e1;
    *reinterpret_cast<float2*>(out + (size_t)i * 2) = make_float2(e0 / s, e1 / s);
}

// ---------------- launch ----------------
extern "C" void kernel_launch(void* const* d_in, const int* in_sizes, int n_in,
                              void* d_out, int out_size) {
    (void)in_sizes; (void)n_in; (void)out_size;
    const float* x     = (const float*)d_in[0];
    const int*   ei    = (const int*)d_in[1];
    const int*   batch = (const int*)d_in[2];
    const float* Wl0 = (const float*)d_in[3];
    const float* bl0 = (const float*)d_in[4];
    const float* Wr0 = (const float*)d_in[5];
    const float* Wl1 = (const float*)d_in[6];
    const float* bl1 = (const float*)d_in[7];
    const float* Wr1 = (const float*)d_in[8];
    const float* Wl2 = (const float*)d_in[9];
    const float* bl2 = (const float*)d_in[10];
    const float* Wr2 = (const float*)d_in[11];
    const float* Wl3 = (const float*)d_in[12];
    const float* bl3 = (const float*)d_in[13];
    const float* Wr3 = (const float*)d_in[14];
    const float* Wf  = (const float*)d_in[15];
    const float* bf  = (const float*)d_in[16];
    float* out = (float*)d_out;

    const int* src = ei;
    const int* dst = ei + N_EDGES;

    __nv_bfloat16 *whi, *wlo, *sah, *sal, *sbh, *sbl, *mh, *ml;
    float *lg, *pl;
    cudaGetSymbolAddress((void**)&whi, g_whi);
    cudaGetSymbolAddress((void**)&wlo, g_wlo);
    cudaGetSymbolAddress((void**)&sah, g_sa_hi);
    cudaGetSymbolAddress((void**)&sal, g_sa_lo);
    cudaGetSymbolAddress((void**)&sbh, g_sb_hi);
    cudaGetSymbolAddress((void**)&sbl, g_sb_lo);
    cudaGetSymbolAddress((void**)&mh, g_msg_hi);
    cudaGetSymbolAddress((void**)&ml, g_msg_lo);
    cudaGetSymbolAddress((void**)&lg, g_logit);
    cudaGetSymbolAddress((void**)&pl, g_pool);

    const int SMEM = 131072;
    cudaFuncSetAttribute(mf_gemm<64, 128, false>,  cudaFuncAttributeMaxDynamicSharedMemorySize, SMEM);
    cudaFuncSetAttribute(mf_gemm<128, 128, false>, cudaFuncAttributeMaxDynamicSharedMemorySize, SMEM);
    cudaFuncSetAttribute(mf_gemm<128, 256, false>, cudaFuncAttributeMaxDynamicSharedMemorySize, SMEM);
    cudaFuncSetAttribute(mf_gemm<256, 256, true>,  cudaFuncAttributeMaxDynamicSharedMemorySize, SMEM);

    const int NB_N = (N_NODES + 255) / 256;
    const int NB_E = (N_EDGES + 255) / 256;
    const int T128 = (N_NODES + 127) / 128;  // 1563

    // degree + CSR + buckets (also zeros per-node logits)
    k_zero_deg<<<NB_N, 256>>>();
    k_deg<<<NB_E, 256>>>(dst);
    k_scan1<<<NBLK_SCAN, 256>>>();
    k_scan2<<<1, 1024>>>();
    k_scan3<<<NB_N, 256>>>();
    k_csr_fill<<<NB_E, 256>>>(src, dst);
    k_bcount<<<NB_N, 256>>>();
    k_offsets<<<1, 1>>>();
    k_fill<<<NB_N, 256>>>();

    // weight prep + x split + pool zero (pool accumulated by L3 GEMM)
    k_prep_w<64, 128><<<(6 * 128 * 128 + 255) / 256, 256>>>(Wl0, Wr0, whi + WOFF0, wlo + WOFF0);
    k_prep_w<128, 128><<<(6 * 256 * 128 + 255) / 256, 256>>>(Wl1, Wr1, whi + WOFF1, wlo + WOFF1);
    k_prep_w<128, 256><<<(6 * 256 * 256 + 255) / 256, 256>>>(Wl2, Wr2, whi + WOFF2, wlo + WOFF2);
    k_prep_w<256, 256><<<(6 * 512 * 256 + 255) / 256, 256>>>(Wl3, Wr3, whi + WOFF3, wlo + WOFF3);
    k_split_x<<<(N_NODES * 8 + 255) / 256, 256>>>(x, sah, sal);
    k_zero_pool<<<(N_GRAPHS * 64 + 255) / 256, 256>>>();

    // layer 0: 64 -> 128   (in sa, out sb)
    k_agg<64><<<(N_NODES * 8 + 255) / 256, 256>>>(sah, sal, mh, ml);
    mf_gemm<64, 128, false><<<dim3(T128, 6), 256, SMEM>>>(sah, sal, whi + WOFF0, wlo + WOFF0, bl0, Wf, 0, sbh, sbl, lg, nullptr, nullptr);

    // layer 1: 128 -> 128  (in sb, out sa)
    k_agg<128><<<(N_NODES * 16 + 255) / 256, 256>>>(sbh, sbl, mh, ml);
    mf_gemm<128, 128, false><<<dim3(T128, 6), 256, SMEM>>>(sbh, sbl, whi + WOFF1, wlo + WOFF1, bl1, Wf, 128, sah, sal, lg, nullptr, nullptr);

    // layer 2: 128 -> 256  (in sa, out sb)
    k_agg<128><<<(N_NODES * 16 + 255) / 256, 256>>>(sah, sal, mh, ml);
    mf_gemm<128, 256, false><<<dim3(T128 * 2, 6), 256, SMEM>>>(sah, sal, whi + WOFF2, wlo + WOFF2, bl2, Wf, 256, sbh, sbl, lg, nullptr, nullptr);

    // layer 3: 256 -> 256  (in sb; pool-fused epilogue, no hidden-state store)
    k_agg<256><<<(N_NODES * 32 + 255) / 256, 256>>>(sbh, sbl, mh, ml);
    mf_gemm<256, 256, true><<<dim3(T128 * 2, 6), 256, SMEM>>>(sbh, sbl, whi + WOFF3, wlo + WOFF3, bl3, Wf, 512, nullptr, nullptr, lg, batch, pl);

    // pooled-branch logits + softmax
    k_pool_dot<<<(N_GRAPHS * 32 + 255) / 256, 256>>>(Wf);
    k_finalize<<<NB_N, 256>>>(batch, bf, out);
}

// round 9
// speedup vs baseline: 2.4492x; 1.0345x over previous
#include <cuda_runtime.h>
#include <cuda_bf16.h>
#include <cstdint>

#define N_NODES  200000
#define N_EDGES  800000
#define N_GRAPHS 4096
#define MAXDEG   5
#define NBLK_SCAN 782   // ceil(N_NODES/256)
#define MAX_TILES 1568  // ceil(N_NODES/128) + 5 bucket remainders

// ---------------- scratch (static __device__, no allocs) ----------------
__device__ float g_pool[N_GRAPHS * 256];
__device__ float g_logit[N_NODES * 2];
__device__ float g_glogit[N_GRAPHS * 2];
__device__ __nv_bfloat16 g_msg_hi[N_NODES * 256];
__device__ __nv_bfloat16 g_msg_lo[N_NODES * 256];
__device__ __nv_bfloat16 g_sa_hi[N_NODES * 256];
__device__ __nv_bfloat16 g_sa_lo[N_NODES * 256];
__device__ __nv_bfloat16 g_sb_hi[N_NODES * 256];
__device__ __nv_bfloat16 g_sb_lo[N_NODES * 256];
__device__ int   g_deg[N_NODES];
__device__ int   g_cur[N_NODES];
__device__ int   g_perm[N_NODES];
__device__ int   g_csr_off[N_NODES + 1];
__device__ int   g_csr[N_EDGES];
__device__ int   g_bsum[1024];
__device__ int   g_bpre[1024];
// [0..5] counts, [8..13] offsets, [16..21] cursors, [24..29] tile starts, [30] total tiles
__device__ int   g_meta[64];

// split-bf16 transposed weights: [d][n][k] K-major (k spans 2*CIN: Wl then Wr)
#define WOFF0 0
#define WOFF1 98304
#define WOFF2 294912
#define WOFF3 688128
#define WTOT  1474560
__device__ __nv_bfloat16 g_whi[WTOT];
__device__ __nv_bfloat16 g_wlo[WTOT];

// ---------------- helpers (portable PTX only) ----------------
__device__ __forceinline__ uint32_t smem_u32(const void* p) {
    uint32_t a;
    asm("{ .reg .u64 t; cvta.to.shared.u64 t, %1; cvt.u32.u64 %0, t; }" : "=r"(a) : "l"(p));
    return a;
}
__device__ __forceinline__ void red_add_v2(float* addr, float x, float y) {
    asm volatile("red.global.add.v2.f32 [%0], {%1,%2};"
                 :: "l"(addr), "f"(x), "f"(y) : "memory");
}
__device__ __forceinline__ void ldsm_x4(uint32_t* r, uint32_t addr) {
    asm volatile("ldmatrix.sync.aligned.m8n8.x4.shared.b16 {%0,%1,%2,%3}, [%4];"
                 : "=r"(r[0]), "=r"(r[1]), "=r"(r[2]), "=r"(r[3]) : "r"(addr));
}
__device__ __forceinline__ void ldsm_x2(uint32_t* r, uint32_t addr) {
    asm volatile("ldmatrix.sync.aligned.m8n8.x2.shared.b16 {%0,%1}, [%2];"
                 : "=r"(r[0]), "=r"(r[1]) : "r"(addr));
}
__device__ __forceinline__ void mma_16816(float* c, const uint32_t* a, const uint32_t* b) {
    asm volatile("mma.sync.aligned.m16n8k16.row.col.f32.bf16.bf16.f32 "
                 "{%0,%1,%2,%3}, {%4,%5,%6,%7}, {%8,%9}, {%0,%1,%2,%3};"
                 : "+f"(c[0]), "+f"(c[1]), "+f"(c[2]), "+f"(c[3])
                 : "r"(a[0]), "r"(a[1]), "r"(a[2]), "r"(a[3]), "r"(b[0]), "r"(b[1]));
}
__device__ __forceinline__ void cp_async16(uint32_t s, const void* g, uint32_t sz) {
    asm volatile("cp.async.cg.shared.global [%0], [%1], 16, %2;"
                 :: "r"(s), "l"(g), "r"(sz) : "memory");
}
__device__ __forceinline__ uint32_t pack_hi(float x, float y, float& lx, float& ly) {
    __nv_bfloat16 h0 = __float2bfloat16_rn(x), h1 = __float2bfloat16_rn(y);
    lx = x - __bfloat162float(h0);
    ly = y - __bfloat162float(h1);
    __nv_bfloat162 hp(h0, h1);
    return *reinterpret_cast<uint32_t*>(&hp);
}
__device__ __forceinline__ uint32_t pack_bf2(float x, float y) {
    __nv_bfloat162 p = __floats2bfloat162_rn(x, y);
    return *reinterpret_cast<uint32_t*>(&p);
}
__device__ __forceinline__ float2 upk(uint32_t u) {
    return __bfloat1622float2(*reinterpret_cast<__nv_bfloat162*>(&u));
}

// ---------------- degree / scan / csr / buckets ----------------
__global__ void k_zero_deg() {
    int i = blockIdx.x * 256 + threadIdx.x;
    if (i < N_NODES) {
        g_deg[i] = 0; g_cur[i] = 0;
        *reinterpret_cast<float2*>(g_logit + i * 2) = make_float2(0.f, 0.f);
    }
    if (i < 64) g_meta[i] = 0;
}
__global__ void k_deg(const int* __restrict__ dst) {
    int e = blockIdx.x * 256 + threadIdx.x;
    if (e < N_EDGES) atomicAdd(&g_deg[dst[e]], 1);
}
// scan pass 1 + fused bucket histogram
__global__ void k_scan1() {
    __shared__ int s[256];
    int b = blockIdx.x, t = threadIdx.x, i = b * 256 + t;
    int v = (i < N_NODES) ? g_deg[i] : 0;
    s[t] = v;
    __syncthreads();
#pragma unroll
    for (int o = 1; o < 256; o <<= 1) {
        int u = (t >= o) ? s[t - o] : 0;
        __syncthreads();
        s[t] += u;
        __syncthreads();
    }
    if (i < N_NODES) {
        g_csr_off[i] = s[t] - v;
        atomicAdd(&g_meta[min(v, MAXDEG)], 1);
    }
    if (t == 255) g_bsum[b] = s[255];
}
// scan pass 2 + fused bucket offsets + GEMM tile-prefix starts
__global__ void k_scan2() {
    __shared__ int s[1024];
    int t = threadIdx.x;
    if (t == 0) {
        int so = 0, ts = 0;
#pragma unroll
        for (int d = 0; d <= MAXDEG; d++) {
            int m = g_meta[d];
            g_meta[8 + d]  = so;  so += m;
            g_meta[24 + d] = ts;  ts += (m + 127) >> 7;
        }
        g_meta[30] = ts;
    }
    int v = (t < NBLK_SCAN) ? g_bsum[t] : 0;
    s[t] = v;
    __syncthreads();
#pragma unroll
    for (int o = 1; o < 1024; o <<= 1) {
        int u = (t >= o) ? s[t - o] : 0;
        __syncthreads();
        s[t] += u;
        __syncthreads();
    }
    if (t < NBLK_SCAN) g_bpre[t] = s[t] - v;
}
__global__ void k_scan3() {
    int i = blockIdx.x * 256 + threadIdx.x;
    if (i < N_NODES) g_csr_off[i] += g_bpre[i >> 8];
    if (i == 0) g_csr_off[N_NODES] = N_EDGES;
}
// fused: CSR edge fill (edge domain) + bucket perm fill (node domain)
__global__ void k_fill_all(const int* __restrict__ src, const int* __restrict__ dst) {
    int t = blockIdx.x * 256 + threadIdx.x;
    if (t < N_EDGES) {
        int d = dst[t];
        int p = atomicAdd(&g_cur[d], 1);
        g_csr[g_csr_off[d] + p] = src[t];
    }
    if (t < N_NODES) {
        int dg = min(g_deg[t], MAXDEG);
        int p = atomicAdd(&g_meta[16 + dg], 1);
        g_perm[g_meta[8 + dg] + p] = t;
    }
}

// ---------------- CSR aggregation (split input -> split msg), 2-way MLP ----------------
template <int CIN>
__global__ void k_agg(const __nv_bfloat16* __restrict__ hh, const __nv_bfloat16* __restrict__ hl,
                      __nv_bfloat16* __restrict__ mh, __nv_bfloat16* __restrict__ ml) {
    const int PER = CIN / 8;
    int t = blockIdx.x * 256 + threadIdx.x;
    int node = t / PER, g = t % PER;
    if (node >= N_NODES) return;
    int j0 = g_csr_off[node], j1 = g_csr_off[node + 1];
    float a[8];
#pragma unroll
    for (int i = 0; i < 8; i++) a[i] = 0.f;
    int j = j0;
    for (; j + 2 <= j1; j += 2) {
        int s0 = g_csr[j], s1 = g_csr[j + 1];
        uint4 h0 = *reinterpret_cast<const uint4*>(hh + (size_t)s0 * CIN + g * 8);
        uint4 l0 = *reinterpret_cast<const uint4*>(hl + (size_t)s0 * CIN + g * 8);
        uint4 h1 = *reinterpret_cast<const uint4*>(hh + (size_t)s1 * CIN + g * 8);
        uint4 l1 = *reinterpret_cast<const uint4*>(hl + (size_t)s1 * CIN + g * 8);
        float2 p0 = upk(h0.x), p1 = upk(h0.y), p2 = upk(h0.z), p3 = upk(h0.w);
        float2 q0 = upk(l0.x), q1 = upk(l0.y), q2 = upk(l0.z), q3 = upk(l0.w);
        float2 r0 = upk(h1.x), r1 = upk(h1.y), r2 = upk(h1.z), r3 = upk(h1.w);
        float2 s0v = upk(l1.x), s1v = upk(l1.y), s2v = upk(l1.z), s3v = upk(l1.w);
        a[0] += (p0.x + q0.x) + (r0.x + s0v.x); a[1] += (p0.y + q0.y) + (r0.y + s0v.y);
        a[2] += (p1.x + q1.x) + (r1.x + s1v.x); a[3] += (p1.y + q1.y) + (r1.y + s1v.y);
        a[4] += (p2.x + q2.x) + (r2.x + s2v.x); a[5] += (p2.y + q2.y) + (r2.y + s2v.y);
        a[6] += (p3.x + q3.x) + (r3.x + s3v.x); a[7] += (p3.y + q3.y) + (r3.y + s3v.y);
    }
    if (j < j1) {
        int s0 = g_csr[j];
        uint4 hv = *reinterpret_cast<const uint4*>(hh + (size_t)s0 * CIN + g * 8);
        uint4 lv = *reinterpret_cast<const uint4*>(hl + (size_t)s0 * CIN + g * 8);
        float2 p0 = upk(hv.x), p1 = upk(hv.y), p2 = upk(hv.z), p3 = upk(hv.w);
        float2 q0 = upk(lv.x), q1 = upk(lv.y), q2 = upk(lv.z), q3 = upk(lv.w);
        a[0] += p0.x + q0.x; a[1] += p0.y + q0.y;
        a[2] += p1.x + q1.x; a[3] += p1.y + q1.y;
        a[4] += p2.x + q2.x; a[5] += p2.y + q2.y;
        a[6] += p3.x + q3.x; a[7] += p3.y + q3.y;
    }
    uint4 hw, lw;
    float l0, l1;
    hw.x = pack_hi(a[0], a[1], l0, l1); lw.x = pack_bf2(l0, l1);
    hw.y = pack_hi(a[2], a[3], l0, l1); lw.y = pack_bf2(l0, l1);
    hw.z = pack_hi(a[4], a[5], l0, l1); lw.z = pack_bf2(l0, l1);
    hw.w = pack_hi(a[6], a[7], l0, l1); lw.w = pack_bf2(l0, l1);
    *reinterpret_cast<uint4*>(mh + (size_t)node * CIN + g * 8) = hw;
    *reinterpret_cast<uint4*>(ml + (size_t)node * CIN + g * 8) = lw;
}

// ---------------- fused: x split (node domain) + pool zero ----------------
__global__ void k_splitx_pool(const float* __restrict__ x,
                              __nv_bfloat16* __restrict__ xh, __nv_bfloat16* __restrict__ xl) {
    int t = blockIdx.x * 256 + threadIdx.x;
    if (t < N_GRAPHS * 64)
        reinterpret_cast<float4*>(g_pool)[t] = make_float4(0.f, 0.f, 0.f, 0.f);
    if (t >= N_NODES * 8) return;
    const float4* p = reinterpret_cast<const float4*>(x + (size_t)t * 8);
    float4 v0 = p[0], v1 = p[1];
    uint4 hw, lw;
    float l0, l1;
    hw.x = pack_hi(v0.x, v0.y, l0, l1); lw.x = pack_bf2(l0, l1);
    hw.y = pack_hi(v0.z, v0.w, l0, l1); lw.y = pack_bf2(l0, l1);
    hw.z = pack_hi(v1.x, v1.y, l0, l1); lw.z = pack_bf2(l0, l1);
    hw.w = pack_hi(v1.z, v1.w, l0, l1); lw.w = pack_bf2(l0, l1);
    *reinterpret_cast<uint4*>(xh + (size_t)t * 8) = hw;
    *reinterpret_cast<uint4*>(xl + (size_t)t * 8) = lw;
}

// ---------------- fused weight prep (all 4 layers, one grid) ----------------
__device__ __forceinline__ void prep_one(int t, int CIN, int COUT,
                                         const float* __restrict__ Wl, const float* __restrict__ Wr,
                                         __nv_bfloat16* __restrict__ Whi, __nv_bfloat16* __restrict__ Wlo) {
    int K = 2 * CIN;
    int n = t % COUT;
    int k = (t / COUT) % K;
    int d = t / (COUT * K);
    float v = (k < CIN) ? Wl[((size_t)d * CIN + k) * COUT + n]
                        : Wr[((size_t)d * CIN + (k - CIN)) * COUT + n];
    __nv_bfloat16 hi = __float2bfloat16_rn(v);
    float lo = v - __bfloat162float(hi);
    size_t o = ((size_t)(d * COUT + n)) * K + k;
    Whi[o] = hi;
    Wlo[o] = __float2bfloat16_rn(lo);
}
__global__ void k_prep_all(const float* __restrict__ Wl0, const float* __restrict__ Wr0,
                           const float* __restrict__ Wl1, const float* __restrict__ Wr1,
                           const float* __restrict__ Wl2, const float* __restrict__ Wr2,
                           const float* __restrict__ Wl3, const float* __restrict__ Wr3) {
    int t = blockIdx.x * 256 + threadIdx.x;
    if (t >= WTOT) return;
    if      (t < WOFF1) prep_one(t - WOFF0,  64, 128, Wl0, Wr0, g_whi + WOFF0, g_wlo + WOFF0);
    else if (t < WOFF2) prep_one(t - WOFF1, 128, 128, Wl1, Wr1, g_whi + WOFF1, g_wlo + WOFF1);
    else if (t < WOFF3) prep_one(t - WOFF2, 128, 256, Wl2, Wr2, g_whi + WOFF2, g_wlo + WOFF2);
    else                prep_one(t - WOFF3, 256, 256, Wl3, Wr3, g_whi + WOFF3, g_wlo + WOFF3);
}

// ---------------- pipelined mma.sync bucketed GEMM + fused logit (+pool) epilogue ----------------
// 1D exact tile grid: blockIdx.x = global tile id; bucket resolved via tile-prefix in g_meta[24..30].
template <int CIN, int COUT, bool POOL>
__global__ __launch_bounds__(256, 1)
void mf_gemm(const __nv_bfloat16* __restrict__ hp_hi, const __nv_bfloat16* __restrict__ hp_lo,
             const __nv_bfloat16* __restrict__ Whi, const __nv_bfloat16* __restrict__ Wlo,
             const float* __restrict__ bl,
             const float* __restrict__ Wf, int loff,
             __nv_bfloat16* __restrict__ nx_hi, __nv_bfloat16* __restrict__ nx_lo,
             float* __restrict__ logit,
             const int* __restrict__ batch, float* __restrict__ pool) {
    constexpr int K     = 2 * CIN;
    constexpr int NCH   = K / 64;
    constexpr uint32_t STG = 65536;

    extern __shared__ char smem[];
    __shared__ int rows_s[128];
    __shared__ int bat_s[128];

    const int bx = blockIdx.x;
    if (bx >= g_meta[30]) return;
    int d = 0;
#pragma unroll
    for (int e = 1; e <= MAXDEG; e++)
        if (bx >= g_meta[24 + e]) d = e;
    const int tile = bx - g_meta[24 + d];
    const int slab = blockIdx.y;
    const int M    = g_meta[d];
    const int m0   = tile * 128;
    const int base = g_meta[8 + d];
    const int n0g  = slab * 128;
    const int tid  = threadIdx.x;
    const int lane = tid & 31, wid = tid >> 5;
    const int wm   = wid & 3, wn = wid >> 2;

    if (tid < 128) {
        int mi = m0 + tid;
        int nd = (mi < M) ? g_perm[base + mi] : -1;
        rows_s[tid] = nd;
        if (POOL) bat_s[tid] = (nd >= 0) ? batch[nd] : 0;
    }
    __syncthreads();

    const uint32_t sb = smem_u32(smem);

    auto load_chunk = [&](int c, int buf) {
        const __nv_bfloat16 *ah, *al;
        int kl;
        if (c * 64 < CIN) { ah = g_msg_hi; al = g_msg_lo; kl = c * 64; }
        else              { ah = hp_hi;    al = hp_lo;    kl = c * 64 - CIN; }
        uint32_t s0 = sb + buf * STG;
#pragma unroll
        for (int it = 0; it < 4; it++) {
            int idx = it * 256 + tid;
            int row = idx >> 3, seg = idx & 7;
            int node = rows_s[row];
            uint32_t doff = (uint32_t)(row * 128) + (uint32_t)((seg * 16) ^ ((row & 7) << 4));
            size_t go = (size_t)(node < 0 ? 0 : node) * CIN + kl + seg * 8;
            uint32_t sz = (node < 0) ? 0u : 16u;
            cp_async16(s0 + doff, ah + go, sz);
            cp_async16(s0 + 16384 + doff, al + go, sz);
        }
#pragma unroll
        for (int it = 0; it < 4; it++) {
            int idx = it * 256 + tid;
            int n = idx >> 3, seg = idx & 7;
            uint32_t doff = (uint32_t)(n * 128) + (uint32_t)((seg * 16) ^ ((n & 7) << 4));
            size_t go = ((size_t)(d * COUT + n0g + n)) * K + c * 64 + seg * 8;
            cp_async16(s0 + 32768 + doff, Whi + go, 16);
            cp_async16(s0 + 49152 + doff, Wlo + go, 16);
        }
        asm volatile("cp.async.commit_group;" ::: "memory");
    };

    float acc[2][8][4];
#pragma unroll
    for (int t = 0; t < 2; t++)
#pragma unroll
        for (int u = 0; u < 8; u++)
#pragma unroll
            for (int i = 0; i < 4; i++) acc[t][u][i] = 0.f;

    load_chunk(0, 0);

    for (int c = 0; c < NCH; c++) {
        if (c + 1 < NCH) {
            load_chunk(c + 1, (c + 1) & 1);
            asm volatile("cp.async.wait_group 1;" ::: "memory");
        } else {
            asm volatile("cp.async.wait_group 0;" ::: "memory");
        }
        __syncthreads();

        uint32_t s0 = sb + (uint32_t)(c & 1) * STG;
        uint32_t sAh = s0, sAl = s0 + 16384, sBh = s0 + 32768, sBl = s0 + 49152;
#pragma unroll
        for (int kk = 0; kk < 4; kk++) {
            uint32_t a_hi[2][4], a_lo[2][4];
            const int mrow = wm * 32 + (lane & 15);
            const int kseg = lane >> 4;
#pragma unroll
            for (int t = 0; t < 2; t++) {
                int row = mrow + t * 16;
                uint32_t off = (uint32_t)(row * 128) +
                               (uint32_t)((kk * 32 + kseg * 16) ^ ((row & 7) << 4));
                ldsm_x4(a_hi[t], sAh + off);
                ldsm_x4(a_lo[t], sAl + off);
            }
            const int nlane = wn * 64 + (lane & 7);
            const int bseg  = (lane >> 3) & 1;
            uint32_t b_hi[8][2], b_lo[8][2];
#pragma unroll
            for (int u = 0; u < 8; u++) {
                int n = nlane + u * 8;
                uint32_t off = (uint32_t)(n * 128) +
                               (uint32_t)((kk * 32 + bseg * 16) ^ ((n & 7) << 4));
                ldsm_x2(b_hi[u], sBh + off);
                ldsm_x2(b_lo[u], sBl + off);
            }
#pragma unroll
            for (int t = 0; t < 2; t++)
#pragma unroll
                for (int u = 0; u < 8; u++) {
                    mma_16816(acc[t][u], a_hi[t], b_hi[u]);
                    mma_16816(acc[t][u], a_hi[t], b_lo[u]);
                    mma_16816(acc[t][u], a_lo[t], b_hi[u]);
                }
        }
        __syncthreads();
    }

    // ---- epilogue: bias + (split bf16 out | pool red-add) + fused logit dot ----
    float lgA[2][2], lgB[2][2];
#pragma unroll
    for (int t = 0; t < 2; t++) { lgA[t][0] = lgA[t][1] = lgB[t][0] = lgB[t][1] = 0.f; }

#pragma unroll
    for (int t = 0; t < 2; t++) {
        int r0 = wm * 32 + t * 16 + (lane >> 2);
        int nd0 = rows_s[r0], nd1 = rows_s[r0 + 8];
        int b0 = POOL ? bat_s[r0] : 0, b1 = POOL ? bat_s[r0 + 8] : 0;
#pragma unroll
        for (int u = 0; u < 8; u++) {
            int col = n0g + wn * 64 + u * 8 + (lane & 3) * 2;
            float2 bv = *reinterpret_cast<const float2*>(bl + d * COUT + col);
            float4 wf = *reinterpret_cast<const float4*>(Wf + 2 * (loff + col));
            if (nd0 >= 0) {
                float ox = acc[t][u][0] + bv.x, oy = acc[t][u][1] + bv.y;
                if (POOL) {
                    red_add_v2(pool + (size_t)b0 * 256 + col, ox, oy);
                } else {
                    float lx, ly;
                    uint32_t hw = pack_hi(ox, oy, lx, ly);
                    *reinterpret_cast<uint32_t*>(nx_hi + (size_t)nd0 * COUT + col) = hw;
                    *reinterpret_cast<uint32_t*>(nx_lo + (size_t)nd0 * COUT + col) = pack_bf2(lx, ly);
                }
                lgA[t][0] += ox * wf.x + oy * wf.z;
                lgB[t][0] += ox * wf.y + oy * wf.w;
            }
            if (nd1 >= 0) {
                float ox = acc[t][u][2] + bv.x, oy = acc[t][u][3] + bv.y;
                if (POOL) {
                    red_add_v2(pool + (size_t)b1 * 256 + col, ox, oy);
                } else {
                    float lx, ly;
                    uint32_t hw = pack_hi(ox, oy, lx, ly);
                    *reinterpret_cast<uint32_t*>(nx_hi + (size_t)nd1 * COUT + col) = hw;
                    *reinterpret_cast<uint32_t*>(nx_lo + (size_t)nd1 * COUT + col) = pack_bf2(lx, ly);
                }
                lgA[t][1] += ox * wf.x + oy * wf.z;
                lgB[t][1] += ox * wf.y + oy * wf.w;
            }
        }
    }
#pragma unroll
    for (int t = 0; t < 2; t++)
#pragma unroll
        for (int r = 0; r < 2; r++) {
            float v0 = lgA[t][r], v1 = lgB[t][r];
            v0 += __shfl_xor_sync(0xFFFFFFFFu, v0, 1);
            v0 += __shfl_xor_sync(0xFFFFFFFFu, v0, 2);
            v1 += __shfl_xor_sync(0xFFFFFFFFu, v1, 1);
            v1 += __shfl_xor_sync(0xFFFFFFFFu, v1, 2);
            int rr = wm * 32 + t * 16 + (lane >> 2) + r * 8;
            int nd = rows_s[rr];
            if ((lane & 3) == 0 && nd >= 0) {
                atomicAdd(&logit[nd * 2 + 0], v0);
                atomicAdd(&logit[nd * 2 + 1], v1);
            }
        }
}

// ---------------- pooled-branch logits + finalize ----------------
__global__ void k_pool_dot(const float* __restrict__ Wf) {
    int gt = blockIdx.x * 256 + threadIdx.x;
    int g = gt >> 5, lane = gt & 31;
    if (g >= N_GRAPHS) return;
    float a0 = 0.f, a1 = 0.f;
#pragma unroll
    for (int k = lane; k < 256; k += 32) {
        float v = g_pool[(size_t)g * 256 + k];
        float2 w = *reinterpret_cast<const float2*>(Wf + 2 * (768 + k));
        a0 += v * w.x; a1 += v * w.y;
    }
#pragma unroll
    for (int o = 16; o > 0; o >>= 1) {
        a0 += __shfl_xor_sync(0xFFFFFFFFu, a0, o);
        a1 += __shfl_xor_sync(0xFFFFFFFFu, a1, o);
    }
    if (lane == 0) *reinterpret_cast<float2*>(g_glogit + g * 2) = make_float2(a0, a1);
}
__global__ void k_finalize(const int* __restrict__ batch, const float* __restrict__ bf,
                           float* __restrict__ out) {
    int i = blockIdx.x * 256 + threadIdx.x;
    if (i >= N_NODES) return;
    float2 nl = *reinterpret_cast<const float2*>(g_logit + i * 2);
    float2 gl = *reinterpret_cast<const float2*>(g_glogit + batch[i] * 2);
    float a0 = nl.x + gl.x + bf[0];
    float a1 = nl.y + gl.y + bf[1];
    float m  = fmaxf(a0, a1);
    float e0 = expf(a0 - m), e1 = expf(a1 - m);
    float s  = e0 + e1;
    *reinterpret_cast<float2*>(out + (size_t)i * 2) = make_float2(e0 / s, e1 / s);
}

// ---------------- launch ----------------
extern "C" void kernel_launch(void* const* d_in, const int* in_sizes, int n_in,
                              void* d_out, int out_size) {
    (void)in_sizes; (void)n_in; (void)out_size;
    const float* x     = (const float*)d_in[0];
    const int*   ei    = (const int*)d_in[1];
    const int*   batch = (const int*)d_in[2];
    const float* Wl0 = (const float*)d_in[3];
    const float* bl0 = (const float*)d_in[4];
    const float* Wr0 = (const float*)d_in[5];
    const float* Wl1 = (const float*)d_in[6];
    const float* bl1 = (const float*)d_in[7];
    const float* Wr1 = (const float*)d_in[8];
    const float* Wl2 = (const float*)d_in[9];
    const float* bl2 = (const float*)d_in[10];
    const float* Wr2 = (const float*)d_in[11];
    const float* Wl3 = (const float*)d_in[12];
    const float* bl3 = (const float*)d_in[13];
    const float* Wr3 = (const float*)d_in[14];
    const float* Wf  = (const float*)d_in[15];
    const float* bf  = (const float*)d_in[16];
    float* out = (float*)d_out;

    const int* src = ei;
    const int* dst = ei + N_EDGES;

    __nv_bfloat16 *whi, *wlo, *sah, *sal, *sbh, *sbl, *mh, *ml;
    float *lg, *pl;
    cudaGetSymbolAddress((void**)&whi, g_whi);
    cudaGetSymbolAddress((void**)&wlo, g_wlo);
    cudaGetSymbolAddress((void**)&sah, g_sa_hi);
    cudaGetSymbolAddress((void**)&sal, g_sa_lo);
    cudaGetSymbolAddress((void**)&sbh, g_sb_hi);
    cudaGetSymbolAddress((void**)&sbl, g_sb_lo);
    cudaGetSymbolAddress((void**)&mh, g_msg_hi);
    cudaGetSymbolAddress((void**)&ml, g_msg_lo);
    cudaGetSymbolAddress((void**)&lg, g_logit);
    cudaGetSymbolAddress((void**)&pl, g_pool);

    const int SMEM = 131072;
    cudaFuncSetAttribute(mf_gemm<64, 128, false>,  cudaFuncAttributeMaxDynamicSharedMemorySize, SMEM);
    cudaFuncSetAttribute(mf_gemm<128, 128, false>, cudaFuncAttributeMaxDynamicSharedMemorySize, SMEM);
    cudaFuncSetAttribute(mf_gemm<128, 256, false>, cudaFuncAttributeMaxDynamicSharedMemorySize, SMEM);
    cudaFuncSetAttribute(mf_gemm<256, 256, true>,  cudaFuncAttributeMaxDynamicSharedMemorySize, SMEM);

    const int NB_N = (N_NODES + 255) / 256;
    const int NB_E = (N_EDGES + 255) / 256;

    // degree + CSR + buckets (fused where possible)
    k_zero_deg<<<NB_N, 256>>>();
    k_deg<<<NB_E, 256>>>(dst);
    k_scan1<<<NBLK_SCAN, 256>>>();
    k_scan2<<<1, 1024>>>();
    k_scan3<<<NB_N, 256>>>();
    k_fill_all<<<NB_E, 256>>>(src, dst);

    // weight prep (all layers) + x split + pool zero
    k_prep_all<<<(WTOT + 255) / 256, 256>>>(Wl0, Wr0, Wl1, Wr1, Wl2, Wr2, Wl3, Wr3);
    k_splitx_pool<<<(N_NODES * 8 + 255) / 256, 256>>>(x, sah, sal);

    // layer 0: 64 -> 128   (in sa, out sb)
    k_agg<64><<<(N_NODES * 8 + 255) / 256, 256>>>(sah, sal, mh, ml);
    mf_gemm<64, 128, false><<<dim3(MAX_TILES, 1), 256, SMEM>>>(sah, sal, whi + WOFF0, wlo + WOFF0, bl0, Wf, 0, sbh, sbl, lg, nullptr, nullptr);

    // layer 1: 128 -> 128  (in sb, out sa)
    k_agg<128><<<(N_NODES * 16 + 255) / 256, 256>>>(sbh, sbl, mh, ml);
    mf_gemm<128, 128, false><<<dim3(MAX_TILES, 1), 256, SMEM>>>(sbh, sbl, whi + WOFF1, wlo + WOFF1, bl1, Wf, 128, sah, sal, lg, nullptr, nullptr);

    // layer 2: 128 -> 256  (in sa, out sb)
    k_agg<128><<<(N_NODES * 16 + 255) / 256, 256>>>(sah, sal, mh, ml);
    mf_gemm<128, 256, false><<<dim3(MAX_TILES, 2), 256, SMEM>>>(sah, sal, whi + WOFF2, wlo + WOFF2, bl2, Wf, 256, sbh, sbl, lg, nullptr, nullptr);

    // layer 3: 256 -> 256  (in sb; pool-fused epilogue, no hidden-state store)
    k_agg<256><<<(N_NODES * 32 + 255) / 256, 256>>>(sbh, sbl, mh, ml);
    mf_gemm<256, 256, true><<<dim3(MAX_TILES, 2), 256, SMEM>>>(sbh, sbl, whi + WOFF3, wlo + WOFF3, bl3, Wf, 512, nullptr, nullptr, lg, batch, pl);

    // pooled-branch logits + softmax
    k_pool_dot<<<(N_GRAPHS * 32 + 255) / 256, 256>>>(Wf);
    k_finalize<<<NB_N, 256>>>(batch, bf, out);
}

// round 10
// speedup vs baseline: 2.5530x; 1.0424x over previous
#include <cuda_runtime.h>
#include <cuda_bf16.h>
#include <cstdint>

#define N_NODES  200000
#define N_EDGES  800000
#define N_GRAPHS 4096
#define MAXDEG   5
#define NBLK_SCAN 782   // ceil(N_NODES/256)
#define MAX_TILES 800   // ceil(N_NODES/256) + bucket remainders

// ---------------- scratch (static __device__, no allocs) ----------------
__device__ float g_pool[N_GRAPHS * 256];
__device__ float g_logit[N_NODES * 2];
__device__ float g_glogit[N_GRAPHS * 2];
__device__ __nv_bfloat16 g_msg_hi[N_NODES * 256];
__device__ __nv_bfloat16 g_msg_lo[N_NODES * 256];
__device__ __nv_bfloat16 g_sa_hi[N_NODES * 256];
__device__ __nv_bfloat16 g_sa_lo[N_NODES * 256];
__device__ __nv_bfloat16 g_sb_hi[N_NODES * 256];
__device__ __nv_bfloat16 g_sb_lo[N_NODES * 256];
__device__ int   g_deg[N_NODES];
__device__ int   g_cur[N_NODES];
__device__ int   g_perm[N_NODES];
__device__ int   g_csr_off[N_NODES + 1];
__device__ int   g_csr[N_EDGES];
__device__ int   g_bsum[1024];
__device__ int   g_bpre[1024];
// [0..5] counts, [8..13] offsets, [16..21] cursors, [24..29] tile starts, [30] total tiles
__device__ int   g_meta[64];

// split-bf16 transposed weights: [d][n][k] K-major (k spans 2*CIN: Wl then Wr)
#define WOFF0 0
#define WOFF1 98304
#define WOFF2 294912
#define WOFF3 688128
#define WTOT  1474560
__device__ __nv_bfloat16 g_whi[WTOT];
__device__ __nv_bfloat16 g_wlo[WTOT];

// ---------------- helpers (portable PTX only) ----------------
__device__ __forceinline__ uint32_t smem_u32(const void* p) {
    uint32_t a;
    asm("{ .reg .u64 t; cvta.to.shared.u64 t, %1; cvt.u32.u64 %0, t; }" : "=r"(a) : "l"(p));
    return a;
}
__device__ __forceinline__ void red_add_v2(float* addr, float x, float y) {
    asm volatile("red.global.add.v2.f32 [%0], {%1,%2};"
                 :: "l"(addr), "f"(x), "f"(y) : "memory");
}
__device__ __forceinline__ void ldsm_x4(uint32_t* r, uint32_t addr) {
    asm volatile("ldmatrix.sync.aligned.m8n8.x4.shared.b16 {%0,%1,%2,%3}, [%4];"
                 : "=r"(r[0]), "=r"(r[1]), "=r"(r[2]), "=r"(r[3]) : "r"(addr));
}
__device__ __forceinline__ void mma_16816(float* c, const uint32_t* a, const uint32_t* b) {
    asm volatile("mma.sync.aligned.m16n8k16.row.col.f32.bf16.bf16.f32 "
                 "{%0,%1,%2,%3}, {%4,%5,%6,%7}, {%8,%9}, {%0,%1,%2,%3};"
                 : "+f"(c[0]), "+f"(c[1]), "+f"(c[2]), "+f"(c[3])
                 : "r"(a[0]), "r"(a[1]), "r"(a[2]), "r"(a[3]), "r"(b[0]), "r"(b[1]));
}
__device__ __forceinline__ void cp_async16(uint32_t s, const void* g, uint32_t sz) {
    asm volatile("cp.async.cg.shared.global [%0], [%1], 16, %2;"
                 :: "r"(s), "l"(g), "r"(sz) : "memory");
}
__device__ __forceinline__ uint32_t pack_hi(float x, float y, float& lx, float& ly) {
    __nv_bfloat16 h0 = __float2bfloat16_rn(x), h1 = __float2bfloat16_rn(y);
    lx = x - __bfloat162float(h0);
    ly = y - __bfloat162float(h1);
    __nv_bfloat162 hp(h0, h1);
    return *reinterpret_cast<uint32_t*>(&hp);
}
__device__ __forceinline__ uint32_t pack_bf2(float x, float y) {
    __nv_bfloat162 p = __floats2bfloat162_rn(x, y);
    return *reinterpret_cast<uint32_t*>(&p);
}
__device__ __forceinline__ float2 upk(uint32_t u) {
    return __bfloat1622float2(*reinterpret_cast<__nv_bfloat162*>(&u));
}

// ---------------- degree / scan / csr / buckets ----------------
__global__ void k_zero_deg() {
    int i = blockIdx.x * 256 + threadIdx.x;
    if (i < N_NODES) {
        g_deg[i] = 0; g_cur[i] = 0;
        *reinterpret_cast<float2*>(g_logit + i * 2) = make_float2(0.f, 0.f);
    }
    if (i < 64) g_meta[i] = 0;
}
__global__ void k_deg(const int* __restrict__ dst) {
    int e = blockIdx.x * 256 + threadIdx.x;
    if (e < N_EDGES) atomicAdd(&g_deg[dst[e]], 1);
}
__global__ void k_scan1() {
    __shared__ int s[256];
    int b = blockIdx.x, t = threadIdx.x, i = b * 256 + t;
    int v = (i < N_NODES) ? g_deg[i] : 0;
    s[t] = v;
    __syncthreads();
#pragma unroll
    for (int o = 1; o < 256; o <<= 1) {
        int u = (t >= o) ? s[t - o] : 0;
        __syncthreads();
        s[t] += u;
        __syncthreads();
    }
    if (i < N_NODES) {
        g_csr_off[i] = s[t] - v;
        atomicAdd(&g_meta[min(v, MAXDEG)], 1);
    }
    if (t == 255) g_bsum[b] = s[255];
}
// scan pass 2 + bucket offsets + 256-row GEMM tile-prefix starts
__global__ void k_scan2() {
    __shared__ int s[1024];
    int t = threadIdx.x;
    if (t == 0) {
        int so = 0, ts = 0;
#pragma unroll
        for (int d = 0; d <= MAXDEG; d++) {
            int m = g_meta[d];
            g_meta[8 + d]  = so;  so += m;
            g_meta[24 + d] = ts;  ts += (m + 255) >> 8;
        }
        g_meta[30] = ts;
    }
    int v = (t < NBLK_SCAN) ? g_bsum[t] : 0;
    s[t] = v;
    __syncthreads();
#pragma unroll
    for (int o = 1; o < 1024; o <<= 1) {
        int u = (t >= o) ? s[t - o] : 0;
        __syncthreads();
        s[t] += u;
        __syncthreads();
    }
    if (t < NBLK_SCAN) g_bpre[t] = s[t] - v;
}
__global__ void k_scan3() {
    int i = blockIdx.x * 256 + threadIdx.x;
    if (i < N_NODES) g_csr_off[i] += g_bpre[i >> 8];
    if (i == 0) g_csr_off[N_NODES] = N_EDGES;
}
__global__ void k_fill_all(const int* __restrict__ src, const int* __restrict__ dst) {
    int t = blockIdx.x * 256 + threadIdx.x;
    if (t < N_EDGES) {
        int d = dst[t];
        int p = atomicAdd(&g_cur[d], 1);
        g_csr[g_csr_off[d] + p] = src[t];
    }
    if (t < N_NODES) {
        int dg = min(g_deg[t], MAXDEG);
        int p = atomicAdd(&g_meta[16 + dg], 1);
        g_perm[g_meta[8 + dg] + p] = t;
    }
}

// ---------------- CSR aggregation (split input -> split msg), 2-way MLP ----------------
template <int CIN>
__global__ void k_agg(const __nv_bfloat16* __restrict__ hh, const __nv_bfloat16* __restrict__ hl,
                      __nv_bfloat16* __restrict__ mh, __nv_bfloat16* __restrict__ ml) {
    const int PER = CIN / 8;
    int t = blockIdx.x * 256 + threadIdx.x;
    int node = t / PER, g = t % PER;
    if (node >= N_NODES) return;
    int j0 = g_csr_off[node], j1 = g_csr_off[node + 1];
    float a[8];
#pragma unroll
    for (int i = 0; i < 8; i++) a[i] = 0.f;
    int j = j0;
    for (; j + 2 <= j1; j += 2) {
        int s0 = g_csr[j], s1 = g_csr[j + 1];
        uint4 h0 = *reinterpret_cast<const uint4*>(hh + (size_t)s0 * CIN + g * 8);
        uint4 l0 = *reinterpret_cast<const uint4*>(hl + (size_t)s0 * CIN + g * 8);
        uint4 h1 = *reinterpret_cast<const uint4*>(hh + (size_t)s1 * CIN + g * 8);
        uint4 l1 = *reinterpret_cast<const uint4*>(hl + (size_t)s1 * CIN + g * 8);
        float2 p0 = upk(h0.x), p1 = upk(h0.y), p2 = upk(h0.z), p3 = upk(h0.w);
        float2 q0 = upk(l0.x), q1 = upk(l0.y), q2 = upk(l0.z), q3 = upk(l0.w);
        float2 r0 = upk(h1.x), r1 = upk(h1.y), r2 = upk(h1.z), r3 = upk(h1.w);
        float2 s0v = upk(l1.x), s1v = upk(l1.y), s2v = upk(l1.z), s3v = upk(l1.w);
        a[0] += (p0.x + q0.x) + (r0.x + s0v.x); a[1] += (p0.y + q0.y) + (r0.y + s0v.y);
        a[2] += (p1.x + q1.x) + (r1.x + s1v.x); a[3] += (p1.y + q1.y) + (r1.y + s1v.y);
        a[4] += (p2.x + q2.x) + (r2.x + s2v.x); a[5] += (p2.y + q2.y) + (r2.y + s2v.y);
        a[6] += (p3.x + q3.x) + (r3.x + s3v.x); a[7] += (p3.y + q3.y) + (r3.y + s3v.y);
    }
    if (j < j1) {
        int s0 = g_csr[j];
        uint4 hv = *reinterpret_cast<const uint4*>(hh + (size_t)s0 * CIN + g * 8);
        uint4 lv = *reinterpret_cast<const uint4*>(hl + (size_t)s0 * CIN + g * 8);
        float2 p0 = upk(hv.x), p1 = upk(hv.y), p2 = upk(hv.z), p3 = upk(hv.w);
        float2 q0 = upk(lv.x), q1 = upk(lv.y), q2 = upk(lv.z), q3 = upk(lv.w);
        a[0] += p0.x + q0.x; a[1] += p0.y + q0.y;
        a[2] += p1.x + q1.x; a[3] += p1.y + q1.y;
        a[4] += p2.x + q2.x; a[5] += p2.y + q2.y;
        a[6] += p3.x + q3.x; a[7] += p3.y + q3.y;
    }
    uint4 hw, lw;
    float l0, l1;
    hw.x = pack_hi(a[0], a[1], l0, l1); lw.x = pack_bf2(l0, l1);
    hw.y = pack_hi(a[2], a[3], l0, l1); lw.y = pack_bf2(l0, l1);
    hw.z = pack_hi(a[4], a[5], l0, l1); lw.z = pack_bf2(l0, l1);
    hw.w = pack_hi(a[6], a[7], l0, l1); lw.w = pack_bf2(l0, l1);
    *reinterpret_cast<uint4*>(mh + (size_t)node * CIN + g * 8) = hw;
    *reinterpret_cast<uint4*>(ml + (size_t)node * CIN + g * 8) = lw;
}

// ---------------- fused: x split + pool zero ----------------
__global__ void k_splitx_pool(const float* __restrict__ x,
                              __nv_bfloat16* __restrict__ xh, __nv_bfloat16* __restrict__ xl) {
    int t = blockIdx.x * 256 + threadIdx.x;
    if (t < N_GRAPHS * 64)
        reinterpret_cast<float4*>(g_pool)[t] = make_float4(0.f, 0.f, 0.f, 0.f);
    if (t >= N_NODES * 8) return;
    const float4* p = reinterpret_cast<const float4*>(x + (size_t)t * 8);
    float4 v0 = p[0], v1 = p[1];
    uint4 hw, lw;
    float l0, l1;
    hw.x = pack_hi(v0.x, v0.y, l0, l1); lw.x = pack_bf2(l0, l1);
    hw.y = pack_hi(v0.z, v0.w, l0, l1); lw.y = pack_bf2(l0, l1);
    hw.z = pack_hi(v1.x, v1.y, l0, l1); lw.z = pack_bf2(l0, l1);
    hw.w = pack_hi(v1.z, v1.w, l0, l1); lw.w = pack_bf2(l0, l1);
    *reinterpret_cast<uint4*>(xh + (size_t)t * 8) = hw;
    *reinterpret_cast<uint4*>(xl + (size_t)t * 8) = lw;
}

// ---------------- fused weight prep ----------------
__device__ __forceinline__ void prep_one(int t, int CIN, int COUT,
                                         const float* __restrict__ Wl, const float* __restrict__ Wr,
                                         __nv_bfloat16* __restrict__ Whi, __nv_bfloat16* __restrict__ Wlo) {
    int K = 2 * CIN;
    int n = t % COUT;
    int k = (t / COUT) % K;
    int d = t / (COUT * K);
    float v = (k < CIN) ? Wl[((size_t)d * CIN + k) * COUT + n]
                        : Wr[((size_t)d * CIN + (k - CIN)) * COUT + n];
    __nv_bfloat16 hi = __float2bfloat16_rn(v);
    float lo = v - __bfloat162float(hi);
    size_t o = ((size_t)(d * COUT + n)) * K + k;
    Whi[o] = hi;
    Wlo[o] = __float2bfloat16_rn(lo);
}
__global__ void k_prep_all(const float* __restrict__ Wl0, const float* __restrict__ Wr0,
                           const float* __restrict__ Wl1, const float* __restrict__ Wr1,
                           const float* __restrict__ Wl2, const float* __restrict__ Wr2,
                           const float* __restrict__ Wl3, const float* __restrict__ Wr3) {
    int t = blockIdx.x * 256 + threadIdx.x;
    if (t >= WTOT) return;
    if      (t < WOFF1) prep_one(t - WOFF0,  64, 128, Wl0, Wr0, g_whi + WOFF0, g_wlo + WOFF0);
    else if (t < WOFF2) prep_one(t - WOFF1, 128, 128, Wl1, Wr1, g_whi + WOFF1, g_wlo + WOFF1);
    else if (t < WOFF3) prep_one(t - WOFF2, 128, 256, Wl2, Wr2, g_whi + WOFF2, g_wlo + WOFF2);
    else                prep_one(t - WOFF3, 256, 256, Wl3, Wr3, g_whi + WOFF3, g_wlo + WOFF3);
}

// ---------------- pipelined mma.sync bucketed GEMM (256x128 tile, 64x64 warp tile) ----------------
// 1D exact tile grid (256-row tiles); warps 4(M) x 2(N); fused logit (+pool) epilogue.
template <int CIN, int COUT, bool POOL>
__global__ __launch_bounds__(256, 1)
void mf_gemm(const __nv_bfloat16* __restrict__ hp_hi, const __nv_bfloat16* __restrict__ hp_lo,
             const __nv_bfloat16* __restrict__ Whi, const __nv_bfloat16* __restrict__ Wlo,
             const float* __restrict__ bl,
             const float* __restrict__ Wf, int loff,
             __nv_bfloat16* __restrict__ nx_hi, __nv_bfloat16* __restrict__ nx_lo,
             float* __restrict__ logit,
             const int* __restrict__ batch, float* __restrict__ pool) {
    constexpr int K   = 2 * CIN;
    constexpr int NCH = K / 64;
    constexpr uint32_t STG = 98304;   // per-stage: A_hi 32K | A_lo 32K | B_hi 16K | B_lo 16K

    extern __shared__ char smem[];
    __shared__ int rows_s[256];
    __shared__ int bat_s[256];

    const int bx = blockIdx.x;
    if (bx >= g_meta[30]) return;
    int d = 0;
#pragma unroll
    for (int e = 1; e <= MAXDEG; e++)
        if (bx >= g_meta[24 + e]) d = e;
    const int tile = bx - g_meta[24 + d];
    const int slab = blockIdx.y;
    const int M    = g_meta[d];
    const int m0   = tile * 256;
    const int base = g_meta[8 + d];
    const int n0g  = slab * 128;
    const int tid  = threadIdx.x;
    const int lane = tid & 31, wid = tid >> 5;
    const int wm   = wid & 3, wn = wid >> 2;

    {
        int mi = m0 + tid;
        int nd = (mi < M) ? g_perm[base + mi] : -1;
        rows_s[tid] = nd;
        if (POOL) bat_s[tid] = (nd >= 0) ? batch[nd] : 0;
    }
    __syncthreads();

    const uint32_t sb = smem_u32(smem);

    auto load_chunk = [&](int c, int buf) {
        const __nv_bfloat16 *ah, *al;
        int kl;
        if (c * 64 < CIN) { ah = g_msg_hi; al = g_msg_lo; kl = c * 64; }
        else              { ah = hp_hi;    al = hp_lo;    kl = c * 64 - CIN; }
        uint32_t s0 = sb + buf * STG;
#pragma unroll
        for (int it = 0; it < 8; it++) {
            int idx = it * 256 + tid;
            int row = idx >> 3, seg = idx & 7;
            int node = rows_s[row];
            uint32_t doff = (uint32_t)(row * 128) + (uint32_t)((seg * 16) ^ ((row & 7) << 4));
            size_t go = (size_t)(node < 0 ? 0 : node) * CIN + kl + seg * 8;
            uint32_t sz = (node < 0) ? 0u : 16u;
            cp_async16(s0 + doff, ah + go, sz);
            cp_async16(s0 + 32768 + doff, al + go, sz);
        }
#pragma unroll
        for (int it = 0; it < 4; it++) {
            int idx = it * 256 + tid;
            int n = idx >> 3, seg = idx & 7;
            uint32_t doff = (uint32_t)(n * 128) + (uint32_t)((seg * 16) ^ ((n & 7) << 4));
            size_t go = ((size_t)(d * COUT + n0g + n)) * K + c * 64 + seg * 8;
            cp_async16(s0 + 65536 + doff, Whi + go, 16);
            cp_async16(s0 + 81920 + doff, Wlo + go, 16);
        }
        asm volatile("cp.async.commit_group;" ::: "memory");
    };

    float acc[4][8][4];
#pragma unroll
    for (int t = 0; t < 4; t++)
#pragma unroll
        for (int u = 0; u < 8; u++)
#pragma unroll
            for (int i = 0; i < 4; i++) acc[t][u][i] = 0.f;

    load_chunk(0, 0);

    for (int c = 0; c < NCH; c++) {
        if (c + 1 < NCH) {
            load_chunk(c + 1, (c + 1) & 1);
            asm volatile("cp.async.wait_group 1;" ::: "memory");
        } else {
            asm volatile("cp.async.wait_group 0;" ::: "memory");
        }
        __syncthreads();

        uint32_t s0 = sb + (uint32_t)(c & 1) * STG;
        uint32_t sAh = s0, sAl = s0 + 32768, sBh = s0 + 65536, sBl = s0 + 81920;
#pragma unroll
        for (int kk = 0; kk < 4; kk++) {
            // A frags: 4 m-subtiles of 16 rows, hi+lo
            uint32_t a_hi[4][4], a_lo[4][4];
            const int mrow = wm * 64 + (lane & 15);
            const int kseg = lane >> 4;
#pragma unroll
            for (int t = 0; t < 4; t++) {
                int row = mrow + t * 16;
                uint32_t off = (uint32_t)(row * 128) +
                               (uint32_t)((kk * 32 + kseg * 16) ^ ((row & 7) << 4));
                ldsm_x4(a_hi[t], sAh + off);
                ldsm_x4(a_lo[t], sAl + off);
            }
            // B frags: 8 n-subtiles, processed in 4 pairs via ldsm.x4
            const int bn = wn * 64 + ((lane >> 4) & 1) * 8 + (lane & 7);
            const int bk = kk * 32 + ((lane >> 3) & 1) * 16;
#pragma unroll
            for (int u2 = 0; u2 < 4; u2++) {
                int n = bn + u2 * 16;
                uint32_t off = (uint32_t)(n * 128) + (uint32_t)(bk ^ ((n & 7) << 4));
                uint32_t bh[4], blr[4];
                ldsm_x4(bh, sBh + off);
                ldsm_x4(blr, sBl + off);
#pragma unroll
                for (int t = 0; t < 4; t++) {
                    mma_16816(acc[t][u2 * 2 + 0], a_hi[t], bh + 0);
                    mma_16816(acc[t][u2 * 2 + 0], a_hi[t], blr + 0);
                    mma_16816(acc[t][u2 * 2 + 0], a_lo[t], bh + 0);
                    mma_16816(acc[t][u2 * 2 + 1], a_hi[t], bh + 2);
                    mma_16816(acc[t][u2 * 2 + 1], a_hi[t], blr + 2);
                    mma_16816(acc[t][u2 * 2 + 1], a_lo[t], bh + 2);
                }
            }
        }
        __syncthreads();
    }

    // ---- epilogue: bias + (split bf16 out | pool red-add) + fused logit dot ----
    float lgA[4][2], lgB[4][2];
#pragma unroll
    for (int t = 0; t < 4; t++) { lgA[t][0] = lgA[t][1] = lgB[t][0] = lgB[t][1] = 0.f; }

#pragma unroll
    for (int t = 0; t < 4; t++) {
        int r0 = wm * 64 + t * 16 + (lane >> 2);
        int nd0 = rows_s[r0], nd1 = rows_s[r0 + 8];
        int b0 = POOL ? bat_s[r0] : 0, b1 = POOL ? bat_s[r0 + 8] : 0;
#pragma unroll
        for (int u = 0; u < 8; u++) {
            int col = n0g + wn * 64 + u * 8 + (lane & 3) * 2;
            float2 bv = *reinterpret_cast<const float2*>(bl + d * COUT + col);
            float4 wf = *reinterpret_cast<const float4*>(Wf + 2 * (loff + col));
            if (nd0 >= 0) {
                float ox = acc[t][u][0] + bv.x, oy = acc[t][u][1] + bv.y;
                if (POOL) {
                    red_add_v2(pool + (size_t)b0 * 256 + col, ox, oy);
                } else {
                    float lx, ly;
                    uint32_t hw = pack_hi(ox, oy, lx, ly);
                    *reinterpret_cast<uint32_t*>(nx_hi + (size_t)nd0 * COUT + col) = hw;
                    *reinterpret_cast<uint32_t*>(nx_lo + (size_t)nd0 * COUT + col) = pack_bf2(lx, ly);
                }
                lgA[t][0] += ox * wf.x + oy * wf.z;
                lgB[t][0] += ox * wf.y + oy * wf.w;
            }
            if (nd1 >= 0) {
                float ox = acc[t][u][2] + bv.x, oy = acc[t][u][3] + bv.y;
                if (POOL) {
                    red_add_v2(pool + (size_t)b1 * 256 + col, ox, oy);
                } else {
                    float lx, ly;
                    uint32_t hw = pack_hi(ox, oy, lx, ly);
                    *reinterpret_cast<uint32_t*>(nx_hi + (size_t)nd1 * COUT + col) = hw;
                    *reinterpret_cast<uint32_t*>(nx_lo + (size_t)nd1 * COUT + col) = pack_bf2(lx, ly);
                }
                lgA[t][1] += ox * wf.x + oy * wf.z;
                lgB[t][1] += ox * wf.y + oy * wf.w;
            }
        }
    }
#pragma unroll
    for (int t = 0; t < 4; t++)
#pragma unroll
        for (int r = 0; r < 2; r++) {
            float v0 = lgA[t][r], v1 = lgB[t][r];
            v0 += __shfl_xor_sync(0xFFFFFFFFu, v0, 1);
            v0 += __shfl_xor_sync(0xFFFFFFFFu, v0, 2);
            v1 += __shfl_xor_sync(0xFFFFFFFFu, v1, 1);
            v1 += __shfl_xor_sync(0xFFFFFFFFu, v1, 2);
            int rr = wm * 64 + t * 16 + (lane >> 2) + r * 8;
            int nd = rows_s[rr];
            if ((lane & 3) == 0 && nd >= 0) {
                atomicAdd(&logit[nd * 2 + 0], v0);
                atomicAdd(&logit[nd * 2 + 1], v1);
            }
        }
}

// ---------------- pooled-branch logits + finalize ----------------
__global__ void k_pool_dot(const float* __restrict__ Wf) {
    int gt = blockIdx.x * 256 + threadIdx.x;
    int g = gt >> 5, lane = gt & 31;
    if (g >= N_GRAPHS) return;
    float a0 = 0.f, a1 = 0.f;
#pragma unroll
    for (int k = lane; k < 256; k += 32) {
        float v = g_pool[(size_t)g * 256 + k];
        float2 w = *reinterpret_cast<const float2*>(Wf + 2 * (768 + k));
        a0 += v * w.x; a1 += v * w.y;
    }
#pragma unroll
    for (int o = 16; o > 0; o >>= 1) {
        a0 += __shfl_xor_sync(0xFFFFFFFFu, a0, o);
        a1 += __shfl_xor_sync(0xFFFFFFFFu, a1, o);
    }
    if (lane == 0) *reinterpret_cast<float2*>(g_glogit + g * 2) = make_float2(a0, a1);
}
__global__ void k_finalize(const int* __restrict__ batch, const float* __restrict__ bf,
                           float* __restrict__ out) {
    int i = blockIdx.x * 256 + threadIdx.x;
    if (i >= N_NODES) return;
    float2 nl = *reinterpret_cast<const float2*>(g_logit + i * 2);
    float2 gl = *reinterpret_cast<const float2*>(g_glogit + batch[i] * 2);
    float a0 = nl.x + gl.x + bf[0];
    float a1 = nl.y + gl.y + bf[1];
    float m  = fmaxf(a0, a1);
    float e0 = expf(a0 - m), e1 = expf(a1 - m);
    float s  = e0 + e1;
    *reinterpret_cast<float2*>(out + (size_t)i * 2) = make_float2(e0 / s, e1 / s);
}

// ---------------- launch ----------------
extern "C" void kernel_launch(void* const* d_in, const int* in_sizes, int n_in,
                              void* d_out, int out_size) {
    (void)in_sizes; (void)n_in; (void)out_size;
    const float* x     = (const float*)d_in[0];
    const int*   ei    = (const int*)d_in[1];
    const int*   batch = (const int*)d_in[2];
    const float* Wl0 = (const float*)d_in[3];
    const float* bl0 = (const float*)d_in[4];
    const float* Wr0 = (const float*)d_in[5];
    const float* Wl1 = (const float*)d_in[6];
    const float* bl1 = (const float*)d_in[7];
    const float* Wr1 = (const float*)d_in[8];
    const float* Wl2 = (const float*)d_in[9];
    const float* bl2 = (const float*)d_in[10];
    const float* Wr2 = (const float*)d_in[11];
    const float* Wl3 = (const float*)d_in[12];
    const float* bl3 = (const float*)d_in[13];
    const float* Wr3 = (const float*)d_in[14];
    const float* Wf  = (const float*)d_in[15];
    const float* bf  = (const float*)d_in[16];
    float* out = (float*)d_out;

    const int* src = ei;
    const int* dst = ei + N_EDGES;

    __nv_bfloat16 *whi, *wlo, *sah, *sal, *sbh, *sbl, *mh, *ml;
    float *lg, *pl;
    cudaGetSymbolAddress((void**)&whi, g_whi);
    cudaGetSymbolAddress((void**)&wlo, g_wlo);
    cudaGetSymbolAddress((void**)&sah, g_sa_hi);
    cudaGetSymbolAddress((void**)&sal, g_sa_lo);
    cudaGetSymbolAddress((void**)&sbh, g_sb_hi);
    cudaGetSymbolAddress((void**)&sbl, g_sb_lo);
    cudaGetSymbolAddress((void**)&mh, g_msg_hi);
    cudaGetSymbolAddress((void**)&ml, g_msg_lo);
    cudaGetSymbolAddress((void**)&lg, g_logit);
    cudaGetSymbolAddress((void**)&pl, g_pool);

    const int SMEM = 196608;
    cudaFuncSetAttribute(mf_gemm<64, 128, false>,  cudaFuncAttributeMaxDynamicSharedMemorySize, SMEM);
    cudaFuncSetAttribute(mf_gemm<128, 128, false>, cudaFuncAttributeMaxDynamicSharedMemorySize, SMEM);
    cudaFuncSetAttribute(mf_gemm<128, 256, false>, cudaFuncAttributeMaxDynamicSharedMemorySize, SMEM);
    cudaFuncSetAttribute(mf_gemm<256, 256, true>,  cudaFuncAttributeMaxDynamicSharedMemorySize, SMEM);

    const int NB_N = (N_NODES + 255) / 256;
    const int NB_E = (N_EDGES + 255) / 256;

    // degree + CSR + buckets
    k_zero_deg<<<NB_N, 256>>>();
    k_deg<<<NB_E, 256>>>(dst);
    k_scan1<<<NBLK_SCAN, 256>>>();
    k_scan2<<<1, 1024>>>();
    k_scan3<<<NB_N, 256>>>();
    k_fill_all<<<NB_E, 256>>>(src, dst);

    // weight prep + x split + pool zero
    k_prep_all<<<(WTOT + 255) / 256, 256>>>(Wl0, Wr0, Wl1, Wr1, Wl2, Wr2, Wl3, Wr3);
    k_splitx_pool<<<(N_NODES * 8 + 255) / 256, 256>>>(x, sah, sal);

    // layer 0: 64 -> 128   (in sa, out sb)
    k_agg<64><<<(N_NODES * 8 + 255) / 256, 256>>>(sah, sal, mh, ml);
    mf_gemm<64, 128, false><<<dim3(MAX_TILES, 1), 256, SMEM>>>(sah, sal, whi + WOFF0, wlo + WOFF0, bl0, Wf, 0, sbh, sbl, lg, nullptr, nullptr);

    // layer 1: 128 -> 128  (in sb, out sa)
    k_agg<128><<<(N_NODES * 16 + 255) / 256, 256>>>(sbh, sbl, mh, ml);
    mf_gemm<128, 128, false><<<dim3(MAX_TILES, 1), 256, SMEM>>>(sbh, sbl, whi + WOFF1, wlo + WOFF1, bl1, Wf, 128, sah, sal, lg, nullptr, nullptr);

    // layer 2: 128 -> 256  (in sa, out sb)
    k_agg<128><<<(N_NODES * 16 + 255) / 256, 256>>>(sah, sal, mh, ml);
    mf_gemm<128, 256, false><<<dim3(MAX_TILES, 2), 256, SMEM>>>(sah, sal, whi + WOFF2, wlo + WOFF2, bl2, Wf, 256, sbh, sbl, lg, nullptr, nullptr);

    // layer 3: 256 -> 256  (in sb; pool-fused epilogue, no hidden-state store)
    k_agg<256><<<(N_NODES * 32 + 255) / 256, 256>>>(sbh, sbl, mh, ml);
    mf_gemm<256, 256, true><<<dim3(MAX_TILES, 2), 256, SMEM>>>(sbh, sbl, whi + WOFF3, wlo + WOFF3, bl3, Wf, 512, nullptr, nullptr, lg, batch, pl);

    // pooled-branch logits + softmax
    k_pool_dot<<<(N_GRAPHS * 32 + 255) / 256, 256>>>(Wf);
    k_finalize<<<NB_N, 256>>>(batch, bf, out);
}